// round 2
// baseline (speedup 1.0000x reference)
#include <cuda_runtime.h>
#include <cuda_bf16.h>
#include <math.h>

// ---------------------------------------------------------------------------
// Problem constants
// ---------------------------------------------------------------------------
#define B_    4
#define S_    512
#define T_    16
#define D_    512
#define DS_   64
#define V_    32000
#define NTOK  2048              // B_*S_
#define DECAY 0.60653065971263342f   // exp(-1/2)

static const long SPK       = (long)B_ * T_ * S_ * D_;   // 16,777,216 floats
static const long LOGITS_SZ = (long)B_ * S_ * V_;        // 65,536,000 floats
static const long H_SZ      = SPK;

// arena offsets (floats)
static const long OFF_SPK0 = 0;
static const long OFF_SPK1 = SPK;
static const long OFF_XP   = 2 * SPK;
static const long OFF_Q    = 3 * SPK;
static const long OFF_K    = 4 * SPK;
static const long OFF_V    = 5 * SPK;
static const long OFF_HST  = 6 * SPK;
static const long OFF_VS   = OFF_HST + (long)NTOK * DS_;
static const long OFF_VO   = OFF_VS  + (long)NTOK * DS_;
static const long OFF_OU   = OFF_VO  + (long)NTOK * D_;
static const long OFF_HM   = OFF_OU  + (long)NTOK * D_;
static const long OFF_THRS = OFF_HM  + (long)NTOK * D_;
static const long OFF_THRO = OFF_THRS + 64;
static const long OFF_CNTS = OFF_THRO + 512;   // int region
static const long OFF_CNTO = OFF_CNTS + 64;
static const long OFF_FLG  = OFF_CNTO + 512;   // 48 ints: flag0,flag1,flag2
static const long ARENA_TOTAL = OFF_FLG + 48;

__device__ __align__(256) float g_arena[ARENA_TOTAL];

// ---------------------------------------------------------------------------
// Encode: tok = emb[ids]; act = sigmoid(s*tok); ti = clip(rint(10*(1-act)),0,15)
// spikes (B,T,S,D) one-hot over T.  Buffer pre-zeroed by memset.
// ---------------------------------------------------------------------------
__global__ void encode_k(const int* __restrict__ ids, const float* __restrict__ emb,
                         const float* __restrict__ scaling,
                         float* __restrict__ spk, int* __restrict__ flag)
{
    int idx = blockIdx.x * blockDim.x + threadIdx.x;   // over NTOK*D_
    int d   = idx & (D_ - 1);
    int tok = idx >> 9;
    int b   = tok >> 9;
    int s   = tok & (S_ - 1);
    float e = emb[(long)ids[tok] * D_ + d];
    float a = 1.0f / (1.0f + expf(-(*scaling) * e));
    float tr = rintf(10.0f * (1.0f - a));
    int ti = (int)tr;
    if (ti < 0) ti = 0;
    if (ti > T_ - 1) ti = T_ - 1;
    spk[(((long)(b * T_ + ti)) * S_ + s) * D_ + d] = 1.0f;
    flag[ti] = 1;
}

// ---------------------------------------------------------------------------
// SSM state step: su = h@A^T (+ x_t@Bm^T if active); LIF on (v_s, thr_s)
// 16 tokens per block, 64 threads (one per state channel m).
// ---------------------------------------------------------------------------
__global__ __launch_bounds__(64)
void step_state_k(const float* __restrict__ spk_in, int t,
                  const float* __restrict__ Amat, const float* __restrict__ Bmat,
                  float* __restrict__ hstate, float* __restrict__ vs,
                  const float* __restrict__ thr_s, int* __restrict__ cnt,
                  const int* __restrict__ flag)
{
    __shared__ float xs[16][D_];
    __shared__ float hs[16][DS_];
    const int m    = threadIdx.x;
    const int tok0 = blockIdx.x * 16;
    const int active = flag[0];

    for (int tk = 0; tk < 16; ++tk)
        hs[tk][m] = hstate[(long)(tok0 + tk) * DS_ + m];
    if (active) {
        for (int i = m; i < 16 * D_; i += 64) {
            int tk = i >> 9, d = i & (D_ - 1);
            int tok = tok0 + tk;
            int b = tok >> 9, s = tok & (S_ - 1);
            xs[tk][d] = spk_in[(((long)(b * T_ + t)) * S_ + s) * D_ + d];
        }
    }
    __syncthreads();

    float acc[16];
#pragma unroll
    for (int tk = 0; tk < 16; ++tk) acc[tk] = 0.0f;

    for (int n = 0; n < DS_; ++n) {
        float a = Amat[m * DS_ + n];
#pragma unroll
        for (int tk = 0; tk < 16; ++tk) acc[tk] += hs[tk][n] * a;
    }
    if (active) {
        for (int d = 0; d < D_; ++d) {
            float bv = Bmat[m * D_ + d];
#pragma unroll
            for (int tk = 0; tk < 16; ++tk) acc[tk] += xs[tk][d] * bv;
        }
    }

    const float thr = thr_s[m];
    int c = 0;
#pragma unroll
    for (int tk = 0; tk < 16; ++tk) {
        long idx = (long)(tok0 + tk) * DS_ + m;
        float v = vs[idx] * DECAY + acc[tk];
        float sp = (v - thr >= 0.0f) ? 1.0f : 0.0f;
        v *= (1.0f - sp);
        vs[idx] = v;
        hstate[idx] = sp;
        c += (int)sp;
    }
    if (c) atomicAdd(&cnt[m], c);
}

// thr += 0.1*(count/2048 - 0.1)  (guarded by active flag if provided)
__global__ void thr_update_k(float* __restrict__ thr, const int* __restrict__ cnt,
                             int n, const int* __restrict__ flag)
{
    if (flag && flag[0] == 0) return;
    int i = blockIdx.x * blockDim.x + threadIdx.x;
    if (i < n) {
        float mean = (float)cnt[i] * (1.0f / 2048.0f);
        thr[i] += 0.1f * (mean - 0.1f);
    }
}

// ---------------------------------------------------------------------------
// Output LIF (active steps only): v_o = v_o*decay + ou; spike; write (B,T,S,D)
// 512 threads (one per channel e), 32 tokens per block.
// ---------------------------------------------------------------------------
__global__ __launch_bounds__(512)
void out_lif_k(const float* __restrict__ ou, float* __restrict__ vo,
               const float* __restrict__ thr_o, float* __restrict__ spk_out, int t,
               int* __restrict__ cnt, int* __restrict__ flagOut,
               const int* __restrict__ flagIn)
{
    if (flagIn[0] == 0) return;
    const int e    = threadIdx.x;
    const int tok0 = blockIdx.x * 32;
    const float thr = thr_o[e];
    int c = 0;
    for (int tk = 0; tk < 32; ++tk) {
        int tok = tok0 + tk;
        int b = tok >> 9, s = tok & (S_ - 1);
        long idx = (long)tok * D_ + e;
        float v = vo[idx] * DECAY + ou[idx];
        float sp = (v - thr >= 0.0f) ? 1.0f : 0.0f;
        v *= (1.0f - sp);
        vo[idx] = v;
        spk_out[(((long)(b * T_ + t)) * S_ + s) * D_ + e] = sp;
        c += (int)sp;
    }
    if (c) { atomicAdd(&cnt[e], c); flagOut[0] = 1; }
}

__global__ void init_thr_k(float* __restrict__ thr_s, float* __restrict__ thr_o)
{
    int i = threadIdx.x;
    if (i < 64) thr_s[i] = 1.0f;
    thr_o[i] = 1.0f;
}

// ---------------------------------------------------------------------------
// Generic SGEMM: C[M,N] = A @ W^T (+ bias) (+ C)
// W row-major (N,K).  A row addressing: off(row) = (row/sdiv)*outer +
// (row%sdiv)*inner + cst   (handles both contiguous and time-sliced layouts).
// 128x128x8 tile, 256 threads, 8x8 per thread.  Requires M%128==N%128==K%8==0.
// ---------------------------------------------------------------------------
template<bool ACC, bool HASBIAS>
__global__ __launch_bounds__(256)
void sgemm_k(const float* __restrict__ A, const float* __restrict__ W,
             const float* __restrict__ bias, float* __restrict__ C,
             int M, int N, int K,
             long aOuter, long aInner, long aConst, int aSdiv,
             const int* __restrict__ flag)
{
    if (flag && flag[0] == 0) return;
    __shared__ float As[8][128];
    __shared__ float Bs[8][128];
    const int tid = threadIdx.x;
    const int bx = blockIdx.x, by = blockIdx.y;
    const int tx = tid & 15, ty = tid >> 4;

    const int lrow = tid >> 1;
    const int lk4  = (tid & 1) * 4;

    const int arow = by * 128 + lrow;
    const long aoff = (long)(arow / aSdiv) * aOuter + (long)(arow % aSdiv) * aInner + aConst;
    const float* Aptr = A + aoff + lk4;
    const float* Wptr = W + (long)(bx * 128 + lrow) * K + lk4;

    float acc[8][8];
#pragma unroll
    for (int i = 0; i < 8; ++i)
#pragma unroll
        for (int j = 0; j < 8; ++j) acc[i][j] = 0.0f;

    for (int k0 = 0; k0 < K; k0 += 8) {
        float4 av = *(const float4*)(Aptr + k0);
        float4 wv = *(const float4*)(Wptr + k0);
        As[lk4 + 0][lrow] = av.x; As[lk4 + 1][lrow] = av.y;
        As[lk4 + 2][lrow] = av.z; As[lk4 + 3][lrow] = av.w;
        Bs[lk4 + 0][lrow] = wv.x; Bs[lk4 + 1][lrow] = wv.y;
        Bs[lk4 + 2][lrow] = wv.z; Bs[lk4 + 3][lrow] = wv.w;
        __syncthreads();
#pragma unroll
        for (int k = 0; k < 8; ++k) {
            float ar[8], br[8];
            *(float4*)&ar[0] = *(const float4*)&As[k][ty * 4];
            *(float4*)&ar[4] = *(const float4*)&As[k][64 + ty * 4];
            *(float4*)&br[0] = *(const float4*)&Bs[k][tx * 4];
            *(float4*)&br[4] = *(const float4*)&Bs[k][64 + tx * 4];
#pragma unroll
            for (int i = 0; i < 8; ++i)
#pragma unroll
                for (int j = 0; j < 8; ++j)
                    acc[i][j] += ar[i] * br[j];
        }
        __syncthreads();
    }

#pragma unroll
    for (int i = 0; i < 8; ++i) {
        int row = by * 128 + ((i < 4) ? (ty * 4 + i) : (64 + ty * 4 + (i - 4)));
        float* crow = C + (long)row * N + bx * 128;
#pragma unroll
        for (int half = 0; half < 2; ++half) {
            int colbase = half * 64 + tx * 4;
            float4 r;
            r.x = acc[i][half * 4 + 0]; r.y = acc[i][half * 4 + 1];
            r.z = acc[i][half * 4 + 2]; r.w = acc[i][half * 4 + 3];
            if (HASBIAS) {
                float4 bv = *(const float4*)(bias + bx * 128 + colbase);
                r.x += bv.x; r.y += bv.y; r.z += bv.z; r.w += bv.w;
            }
            if (ACC) {
                float4 ov = *(const float4*)(crow + colbase);
                r.x += ov.x; r.y += ov.y; r.z += ov.z; r.w += ov.w;
            }
            *(float4*)(crow + colbase) = r;
        }
    }
}

// ---------------------------------------------------------------------------
// (B,T,S,D) -> (B,S,T,D) permute (D rows intact; both sides coalesced)
// ---------------------------------------------------------------------------
__global__ void transpose_k(const float* __restrict__ x, float* __restrict__ xp)
{
    long idx = (long)blockIdx.x * blockDim.x + threadIdx.x;  // output index
    int d = idx & (D_ - 1);
    long r = idx >> 9;
    int t = (int)(r & (T_ - 1));
    long r2 = r >> 4;
    int s = (int)(r2 & (S_ - 1));
    int b = (int)(r2 >> 9);
    xp[idx] = x[(((long)(b * T_ + t)) * S_ + s) * D_ + d];
}

// ---------------------------------------------------------------------------
// Attention core per (token, head): 16x16 scores, softmax over u, av.
// ---------------------------------------------------------------------------
__global__ __launch_bounds__(128)
void attn_core_k(const float* __restrict__ q, const float* __restrict__ k,
                 const float* __restrict__ v, float* __restrict__ av)
{
    __shared__ float qs[16][128], ks[16][128], vsm[16][128];
    __shared__ float sc[16][17];
    const int tid = threadIdx.x;
    const long token = blockIdx.x >> 2;
    const int h = blockIdx.x & 3;
    const long base = token * 16 * 512 + h * 128;

#pragma unroll
    for (int t = 0; t < 16; ++t) {
        qs[t][tid]  = q[base + (long)t * 512 + tid];
        ks[t][tid]  = k[base + (long)t * 512 + tid];
        vsm[t][tid] = v[base + (long)t * 512 + tid];
    }
    __syncthreads();

    for (int p = tid; p < 256; p += 128) {
        int t = p >> 4, u = p & 15;
        float acc = 0.0f;
#pragma unroll
        for (int d = 0; d < 128; ++d) acc += qs[t][d] * ks[u][d];
        sc[t][u] = acc / 11.3137084989847612f;   // / sqrt(128)
    }
    __syncthreads();

    if (tid < 16) {
        int t = tid;
        float mx = sc[t][0];
#pragma unroll
        for (int u = 1; u < 16; ++u) mx = fmaxf(mx, sc[t][u]);
        float e[16], sum = 0.0f;
#pragma unroll
        for (int u = 0; u < 16; ++u) { e[u] = expf(sc[t][u] - mx); sum += e[u]; }
#pragma unroll
        for (int u = 0; u < 16; ++u) sc[t][u] = e[u] / sum;
    }
    __syncthreads();

#pragma unroll
    for (int t = 0; t < 16; ++t) {
        float acc = 0.0f;
#pragma unroll
        for (int u = 0; u < 16; ++u) acc += sc[t][u] * vsm[u][tid];
        av[base + (long)t * 512 + tid] = acc;
    }
}

// ---------------------------------------------------------------------------
// h = x + permute(out_attn); hmean = mean_t(h)
// ---------------------------------------------------------------------------
__global__ void finalize_k(const float* __restrict__ xspk, const float* __restrict__ oat,
                           float* __restrict__ hout, float* __restrict__ hmean)
{
    int idx = blockIdx.x * blockDim.x + threadIdx.x;  // over NTOK*D_
    int d   = idx & (D_ - 1);
    int tok = idx >> 9;
    int b   = tok >> 9;
    int s   = tok & (S_ - 1);
    float sum = 0.0f;
#pragma unroll
    for (int t = 0; t < 16; ++t) {
        long hidx = (((long)(b * T_ + t)) * S_ + s) * D_ + d;
        float val = xspk[hidx] + oat[(((long)tok) * T_ + t) * D_ + d];
        hout[hidx] = val;
        sum += val;
    }
    hmean[(long)tok * D_ + d] = sum * (1.0f / 16.0f);
}

// ---------------------------------------------------------------------------
// host
// ---------------------------------------------------------------------------
static inline void gemm_plain(const float* A, const float* W, const float* bias,
                              float* C, int M, int N, int K, bool acc,
                              const int* flag)
{
    dim3 grid(N / 128, M / 128);
    if (acc) {
        sgemm_k<true, false><<<grid, 256>>>(A, W, bias, C, M, N, K,
                                            (long)M * K, K, 0L, M, flag);
    } else if (bias) {
        sgemm_k<false, true><<<grid, 256>>>(A, W, bias, C, M, N, K,
                                            (long)M * K, K, 0L, M, flag);
    } else {
        sgemm_k<false, false><<<grid, 256>>>(A, W, bias, C, M, N, K,
                                             (long)M * K, K, 0L, M, flag);
    }
}

extern "C" void kernel_launch(void* const* d_in, const int* in_sizes, int n_in,
                              void* d_out, int out_size)
{
    const int*   ids  = (const int*)d_in[0];
    const float* emb  = (const float*)d_in[1];
    const float* scal = (const float*)d_in[2];
    const float* Aall = (const float*)d_in[3];
    const float* Ball = (const float*)d_in[4];
    const float* Call = (const float*)d_in[5];
    const float* Dall = (const float*)d_in[6];
    const float* wq = (const float*)d_in[7];   const float* bq = (const float*)d_in[8];
    const float* wk = (const float*)d_in[9];   const float* bk = (const float*)d_in[10];
    const float* wv = (const float*)d_in[11];  const float* bv = (const float*)d_in[12];
    const float* wo = (const float*)d_in[13];  const float* bo = (const float*)d_in[14];
    const float* wout = (const float*)d_in[15];const float* bout = (const float*)d_in[16];
    float* out = (float*)d_out;

    float* arena = nullptr;
    cudaGetSymbolAddress((void**)&arena, g_arena);

    float* spk0   = arena + OFF_SPK0;
    float* spk1   = arena + OFF_SPK1;
    float* xp     = arena + OFF_XP;
    float* qb     = arena + OFF_Q;
    float* kb     = arena + OFF_K;
    float* vb     = arena + OFF_V;
    float* hstate = arena + OFF_HST;
    float* vs     = arena + OFF_VS;
    float* vo     = arena + OFF_VO;
    float* ou     = arena + OFF_OU;
    float* hmean  = arena + OFF_HM;
    float* thr_s  = arena + OFF_THRS;
    float* thr_o  = arena + OFF_THRO;
    int*   cnt_s  = (int*)(arena + OFF_CNTS);
    int*   flags  = (int*)(arena + OFF_FLG);   // flag0[16], flag1[16], flag2[16]
    int*   cnt_o  = (int*)(arena + OFF_CNTO);

    // -------- encode --------
    cudaMemsetAsync(spk0, 0, SPK * sizeof(float));
    cudaMemsetAsync(flags, 0, 48 * sizeof(int));
    encode_k<<<(NTOK * D_) / 256, 256>>>(ids, emb, scal, spk0, flags);

    // -------- SSM layers --------
    for (int l = 0; l < 2; ++l) {
        const float* Al = Aall + (long)l * DS_ * DS_;
        const float* Bl = Ball + (long)l * DS_ * D_;
        const float* Cl = Call + (long)l * D_ * DS_;
        const float* Dl = Dall + (long)l * D_ * D_;
        float* xin  = l ? spk1 : spk0;
        float* xout = l ? spk0 : spk1;
        int* fin  = flags + (l ? 16 : 0);
        int* fout = flags + (l ? 32 : 16);

        cudaMemsetAsync(xout, 0, SPK * sizeof(float));
        cudaMemsetAsync(hstate, 0,
                        ((long)NTOK * DS_ * 2 + (long)NTOK * D_) * sizeof(float));
        init_thr_k<<<1, 512>>>(thr_s, thr_o);

        for (int t = 0; t < T_; ++t) {
            cudaMemsetAsync(cnt_s, 0, (64 + 512) * sizeof(int));
            step_state_k<<<NTOK / 16, 64>>>(xin, t, Al, Bl, hstate, vs,
                                            thr_s, cnt_s, fin + t);
            thr_update_k<<<1, 64>>>(thr_s, cnt_s, 64, nullptr);
            // ou = hstate @ Cl^T  (K=64)
            sgemm_k<false, false><<<dim3(4, 16), 256>>>(
                hstate, Cl, nullptr, ou, NTOK, D_, DS_,
                (long)NTOK * DS_, (long)DS_, 0L, NTOK, fin + t);
            // ou += x_t @ Dl^T  (K=512, time-sliced A layout)
            sgemm_k<true, false><<<dim3(4, 16), 256>>>(
                xin, Dl, nullptr, ou, NTOK, D_, D_,
                (long)T_ * S_ * D_, (long)D_, (long)t * S_ * D_, S_, fin + t);
            out_lif_k<<<NTOK / 32, 512>>>(ou, vo, thr_o, xout, t,
                                          cnt_o, fout + t, fin + t);
            thr_update_k<<<2, 256>>>(thr_o, cnt_o, 512, fin + t);
        }
    }
    // after 2 layers: attention input = spk0 (B,T,S,D)

    // -------- attention --------
    transpose_k<<<(int)(SPK / 256), 256>>>(spk0, xp);
    const int MA = B_ * S_ * T_;  // 32768
    gemm_plain(xp, wq, bq, qb, MA, D_, D_, false, nullptr);
    gemm_plain(xp, wk, bk, kb, MA, D_, D_, false, nullptr);
    gemm_plain(xp, wv, bv, vb, MA, D_, D_, false, nullptr);
    attn_core_k<<<NTOK * 4, 128>>>(qb, kb, vb, spk1);        // av -> spk1
    gemm_plain(spk1, wo, bo, qb, MA, D_, D_, false, nullptr); // out-proj -> qb

    // -------- residual + mean + outputs --------
    float* hout = ((long)out_size >= LOGITS_SZ + H_SZ) ? (out + LOGITS_SZ) : xp;
    finalize_k<<<(NTOK * D_) / 256, 256>>>(spk0, qb, hout, hmean);

    // logits = hmean @ w_out^T + b_out -> d_out[0 : B*S*V]
    gemm_plain(hmean, wout, bout, out, NTOK, V_, D_, false, nullptr);
}

// round 7
// speedup vs baseline: 1.0358x; 1.0358x over previous
#include <cuda_runtime.h>
#include <cuda_bf16.h>
#include <math.h>

// ---------------------------------------------------------------------------
// Problem constants
// ---------------------------------------------------------------------------
#define B_    4
#define S_    512
#define T_    16
#define D_    512
#define DS_   64
#define V_    32000
#define NTOK  2048              // B_*S_
#define DECAY 0.60653065971263342f   // exp(-1/2)

static const long SPK       = (long)B_ * T_ * S_ * D_;   // 16,777,216 floats
static const long LOGITS_SZ = (long)B_ * S_ * V_;        // 65,536,000 floats
static const long H_SZ      = SPK;

// arena offsets (floats) -- identical to the round-2 passing kernel
static const long OFF_SPK0 = 0;
static const long OFF_SPK1 = SPK;
static const long OFF_XP   = 2 * SPK;
static const long OFF_Q    = 3 * SPK;
static const long OFF_K    = 4 * SPK;
static const long OFF_V    = 5 * SPK;
static const long OFF_HST  = 6 * SPK;
static const long OFF_VS   = OFF_HST + (long)NTOK * DS_;
static const long OFF_VO   = OFF_VS  + (long)NTOK * DS_;
static const long OFF_OU   = OFF_VO  + (long)NTOK * D_;
static const long OFF_HM   = OFF_OU  + (long)NTOK * D_;
static const long OFF_THRS = OFF_HM  + (long)NTOK * D_;
static const long OFF_THRO = OFF_THRS + 64;
static const long OFF_CNTS = OFF_THRO + 512;   // int region
static const long OFF_CNTO = OFF_CNTS + 64;
static const long OFF_FLG  = OFF_CNTO + 512;   // 48 ints
static const long ARENA_TOTAL = OFF_FLG + 48;

__device__ __align__(256) float g_arena[ARENA_TOTAL];

// ===========================================================================
// SSM SECTION -- VERBATIM from the round-2 PASSING kernel. Do not touch:
// these kernels reproduce the exact spike trains that verified at 1.3e-7.
// ===========================================================================

__global__ void encode_k(const int* __restrict__ ids, const float* __restrict__ emb,
                         const float* __restrict__ scaling,
                         float* __restrict__ spk, int* __restrict__ flag)
{
    int idx = blockIdx.x * blockDim.x + threadIdx.x;   // over NTOK*D_
    int d   = idx & (D_ - 1);
    int tok = idx >> 9;
    int b   = tok >> 9;
    int s   = tok & (S_ - 1);
    float e = emb[(long)ids[tok] * D_ + d];
    float a = 1.0f / (1.0f + expf(-(*scaling) * e));
    float tr = rintf(10.0f * (1.0f - a));
    int ti = (int)tr;
    if (ti < 0) ti = 0;
    if (ti > T_ - 1) ti = T_ - 1;
    spk[(((long)(b * T_ + ti)) * S_ + s) * D_ + d] = 1.0f;
    flag[ti] = 1;
}

__global__ __launch_bounds__(64)
void step_state_k(const float* __restrict__ spk_in, int t,
                  const float* __restrict__ Amat, const float* __restrict__ Bmat,
                  float* __restrict__ hstate, float* __restrict__ vs,
                  const float* __restrict__ thr_s, int* __restrict__ cnt,
                  const int* __restrict__ flag)
{
    __shared__ float xs[16][D_];
    __shared__ float hs[16][DS_];
    const int m    = threadIdx.x;
    const int tok0 = blockIdx.x * 16;
    const int active = flag[0];

    for (int tk = 0; tk < 16; ++tk)
        hs[tk][m] = hstate[(long)(tok0 + tk) * DS_ + m];
    if (active) {
        for (int i = m; i < 16 * D_; i += 64) {
            int tk = i >> 9, d = i & (D_ - 1);
            int tok = tok0 + tk;
            int b = tok >> 9, s = tok & (S_ - 1);
            xs[tk][d] = spk_in[(((long)(b * T_ + t)) * S_ + s) * D_ + d];
        }
    }
    __syncthreads();

    float acc[16];
#pragma unroll
    for (int tk = 0; tk < 16; ++tk) acc[tk] = 0.0f;

    for (int n = 0; n < DS_; ++n) {
        float a = Amat[m * DS_ + n];
#pragma unroll
        for (int tk = 0; tk < 16; ++tk) acc[tk] += hs[tk][n] * a;
    }
    if (active) {
        for (int d = 0; d < D_; ++d) {
            float bv = Bmat[m * D_ + d];
#pragma unroll
            for (int tk = 0; tk < 16; ++tk) acc[tk] += xs[tk][d] * bv;
        }
    }

    const float thr = thr_s[m];
    int c = 0;
#pragma unroll
    for (int tk = 0; tk < 16; ++tk) {
        long idx = (long)(tok0 + tk) * DS_ + m;
        float v = vs[idx] * DECAY + acc[tk];
        float sp = (v - thr >= 0.0f) ? 1.0f : 0.0f;
        v *= (1.0f - sp);
        vs[idx] = v;
        hstate[idx] = sp;
        c += (int)sp;
    }
    if (c) atomicAdd(&cnt[m], c);
}

__global__ void thr_update_k(float* __restrict__ thr, const int* __restrict__ cnt,
                             int n, const int* __restrict__ flag)
{
    if (flag && flag[0] == 0) return;
    int i = blockIdx.x * blockDim.x + threadIdx.x;
    if (i < n) {
        float mean = (float)cnt[i] * (1.0f / 2048.0f);
        thr[i] += 0.1f * (mean - 0.1f);
    }
}

__global__ __launch_bounds__(512)
void out_lif_k(const float* __restrict__ ou, float* __restrict__ vo,
               const float* __restrict__ thr_o, float* __restrict__ spk_out, int t,
               int* __restrict__ cnt, int* __restrict__ flagOut,
               const int* __restrict__ flagIn)
{
    if (flagIn[0] == 0) return;
    const int e    = threadIdx.x;
    const int tok0 = blockIdx.x * 32;
    const float thr = thr_o[e];
    int c = 0;
    for (int tk = 0; tk < 32; ++tk) {
        int tok = tok0 + tk;
        int b = tok >> 9, s = tok & (S_ - 1);
        long idx = (long)tok * D_ + e;
        float v = vo[idx] * DECAY + ou[idx];
        float sp = (v - thr >= 0.0f) ? 1.0f : 0.0f;
        v *= (1.0f - sp);
        vo[idx] = v;
        spk_out[(((long)(b * T_ + t)) * S_ + s) * D_ + e] = sp;
        c += (int)sp;
    }
    if (c) { atomicAdd(&cnt[e], c); flagOut[0] = 1; }
}

__global__ void init_thr_k(float* __restrict__ thr_s, float* __restrict__ thr_o)
{
    int i = threadIdx.x;
    if (i < 64) thr_s[i] = 1.0f;
    thr_o[i] = 1.0f;
}

// fp32 SGEMM -- verbatim round-2 (used for the per-step SSM ou GEMMs)
template<bool ACC, bool HASBIAS>
__global__ __launch_bounds__(256)
void sgemm_k(const float* __restrict__ A, const float* __restrict__ W,
             const float* __restrict__ bias, float* __restrict__ C,
             int M, int N, int K,
             long aOuter, long aInner, long aConst, int aSdiv,
             const int* __restrict__ flag)
{
    if (flag && flag[0] == 0) return;
    __shared__ float As[8][128];
    __shared__ float Bs[8][128];
    const int tid = threadIdx.x;
    const int bx = blockIdx.x, by = blockIdx.y;
    const int tx = tid & 15, ty = tid >> 4;

    const int lrow = tid >> 1;
    const int lk4  = (tid & 1) * 4;

    const int arow = by * 128 + lrow;
    const long aoff = (long)(arow / aSdiv) * aOuter + (long)(arow % aSdiv) * aInner + aConst;
    const float* Aptr = A + aoff + lk4;
    const float* Wptr = W + (long)(bx * 128 + lrow) * K + lk4;

    float acc[8][8];
#pragma unroll
    for (int i = 0; i < 8; ++i)
#pragma unroll
        for (int j = 0; j < 8; ++j) acc[i][j] = 0.0f;

    for (int k0 = 0; k0 < K; k0 += 8) {
        float4 av = *(const float4*)(Aptr + k0);
        float4 wv = *(const float4*)(Wptr + k0);
        As[lk4 + 0][lrow] = av.x; As[lk4 + 1][lrow] = av.y;
        As[lk4 + 2][lrow] = av.z; As[lk4 + 3][lrow] = av.w;
        Bs[lk4 + 0][lrow] = wv.x; Bs[lk4 + 1][lrow] = wv.y;
        Bs[lk4 + 2][lrow] = wv.z; Bs[lk4 + 3][lrow] = wv.w;
        __syncthreads();
#pragma unroll
        for (int k = 0; k < 8; ++k) {
            float ar[8], br[8];
            *(float4*)&ar[0] = *(const float4*)&As[k][ty * 4];
            *(float4*)&ar[4] = *(const float4*)&As[k][64 + ty * 4];
            *(float4*)&br[0] = *(const float4*)&Bs[k][tx * 4];
            *(float4*)&br[4] = *(const float4*)&Bs[k][64 + tx * 4];
#pragma unroll
            for (int i = 0; i < 8; ++i)
#pragma unroll
                for (int j = 0; j < 8; ++j)
                    acc[i][j] += ar[i] * br[j];
        }
        __syncthreads();
    }

#pragma unroll
    for (int i = 0; i < 8; ++i) {
        int row = by * 128 + ((i < 4) ? (ty * 4 + i) : (64 + ty * 4 + (i - 4)));
        float* crow = C + (long)row * N + bx * 128;
#pragma unroll
        for (int half = 0; half < 2; ++half) {
            int colbase = half * 64 + tx * 4;
            float4 r;
            r.x = acc[i][half * 4 + 0]; r.y = acc[i][half * 4 + 1];
            r.z = acc[i][half * 4 + 2]; r.w = acc[i][half * 4 + 3];
            if (HASBIAS) {
                float4 bv = *(const float4*)(bias + bx * 128 + colbase);
                r.x += bv.x; r.y += bv.y; r.z += bv.z; r.w += bv.w;
            }
            if (ACC) {
                float4 ov = *(const float4*)(crow + colbase);
                r.x += ov.x; r.y += ov.y; r.z += ov.z; r.w += ov.w;
            }
            *(float4*)(crow + colbase) = r;
        }
    }
}

// ===========================================================================
// TENSOR-CORE SECTION -- tf32 split GEMMs for the smooth (non-LIF) paths.
// MODE 1: A exact (binary spikes), W = hi+lo          (2 mma, err ~2^-22 |w|)
// MODE 4: A = hi+lo, W = hi+lo, all 4 products        (fp32-equivalent)
// ===========================================================================
__device__ __forceinline__ unsigned f2tf(float x) {
    unsigned u;
    asm("cvt.rna.tf32.f32 %0, %1;" : "=r"(u) : "f"(x));
    return u;
}

__device__ __forceinline__ void mma8(float* c, const unsigned* a, const unsigned* b) {
    asm volatile(
        "mma.sync.aligned.m16n8k8.row.col.f32.tf32.tf32.f32 "
        "{%0,%1,%2,%3},{%4,%5,%6,%7},{%8,%9},{%0,%1,%2,%3};"
        : "+f"(c[0]), "+f"(c[1]), "+f"(c[2]), "+f"(c[3])
        : "r"(a[0]), "r"(a[1]), "r"(a[2]), "r"(a[3]), "r"(b[0]), "r"(b[1]));
}

template<int MODE, bool HASBIAS>
__global__ __launch_bounds__(256)
void gemm_tf32_k(const float* __restrict__ A, const float* __restrict__ W,
                 const float* __restrict__ bias, float* __restrict__ C,
                 int M, int N, int K)
{
    constexpr int BM = 128, BN = 128, BK = 16;
    constexpr int MT = 4, NT = 4;
    __shared__ float As[BK][BM + 8];
    __shared__ float Bs[BK][BN + 8];

    const int tid  = threadIdx.x;
    const int warp = tid >> 5, lane = tid & 31;
    const int wm = warp & 1, wn = warp >> 1;
    const int mW = wm * 64, nW = wn * 32;
    const int g = lane >> 2, q = lane & 3;
    const int bx = blockIdx.x, by = blockIdx.y;

    const int lr = tid >> 1;
    const int lk = (tid & 1) * 8;
    const float* Ag = A + (long)(by * BM + lr) * K + lk;
    const float* Wg = W + (long)(bx * BN + lr) * K + lk;

    float acc[MT][NT][4];
#pragma unroll
    for (int i = 0; i < MT; ++i)
#pragma unroll
        for (int j = 0; j < NT; ++j)
#pragma unroll
            for (int r = 0; r < 4; ++r) acc[i][j][r] = 0.0f;

    for (int k0 = 0; k0 < K; k0 += BK) {
        float4 a0 = *(const float4*)(Ag + k0);
        float4 a1 = *(const float4*)(Ag + k0 + 4);
        As[lk + 0][lr] = a0.x; As[lk + 1][lr] = a0.y;
        As[lk + 2][lr] = a0.z; As[lk + 3][lr] = a0.w;
        As[lk + 4][lr] = a1.x; As[lk + 5][lr] = a1.y;
        As[lk + 6][lr] = a1.z; As[lk + 7][lr] = a1.w;
        float4 w0 = *(const float4*)(Wg + k0);
        float4 w1 = *(const float4*)(Wg + k0 + 4);
        Bs[lk + 0][lr] = w0.x; Bs[lk + 1][lr] = w0.y;
        Bs[lk + 2][lr] = w0.z; Bs[lk + 3][lr] = w0.w;
        Bs[lk + 4][lr] = w1.x; Bs[lk + 5][lr] = w1.y;
        Bs[lk + 6][lr] = w1.z; Bs[lk + 7][lr] = w1.w;
        __syncthreads();

#pragma unroll
        for (int ks = 0; ks < BK; ks += 8) {
            unsigned ahi[MT][4], alo[MT][4];
            unsigned bhi[NT][2], blo[NT][2];
#pragma unroll
            for (int i = 0; i < MT; ++i) {
                int m = mW + i * 16 + g;
                float x0 = As[ks + q][m];
                float x1 = As[ks + q][m + 8];
                float x2 = As[ks + 4 + q][m];
                float x3 = As[ks + 4 + q][m + 8];
                ahi[i][0] = f2tf(x0); ahi[i][1] = f2tf(x1);
                ahi[i][2] = f2tf(x2); ahi[i][3] = f2tf(x3);
                if (MODE == 4) {
                    alo[i][0] = f2tf(x0 - __uint_as_float(ahi[i][0]));
                    alo[i][1] = f2tf(x1 - __uint_as_float(ahi[i][1]));
                    alo[i][2] = f2tf(x2 - __uint_as_float(ahi[i][2]));
                    alo[i][3] = f2tf(x3 - __uint_as_float(ahi[i][3]));
                }
            }
#pragma unroll
            for (int j = 0; j < NT; ++j) {
                int n = nW + j * 8 + g;
                float y0 = Bs[ks + q][n];
                float y1 = Bs[ks + 4 + q][n];
                bhi[j][0] = f2tf(y0); bhi[j][1] = f2tf(y1);
                blo[j][0] = f2tf(y0 - __uint_as_float(bhi[j][0]));
                blo[j][1] = f2tf(y1 - __uint_as_float(bhi[j][1]));
            }
#pragma unroll
            for (int i = 0; i < MT; ++i)
#pragma unroll
                for (int j = 0; j < NT; ++j) {
                    if (MODE == 4) {
                        mma8(acc[i][j], alo[i], blo[j]);
                        mma8(acc[i][j], alo[i], bhi[j]);
                    }
                    mma8(acc[i][j], ahi[i], blo[j]);
                    mma8(acc[i][j], ahi[i], bhi[j]);
                }
        }
        __syncthreads();
    }

#pragma unroll
    for (int i = 0; i < MT; ++i) {
        int r0 = by * BM + mW + i * 16 + g;
#pragma unroll
        for (int j = 0; j < NT; ++j) {
            int c0 = bx * BN + nW + j * 8 + q * 2;
            float2 lo; lo.x = acc[i][j][0]; lo.y = acc[i][j][1];
            float2 hi; hi.x = acc[i][j][2]; hi.y = acc[i][j][3];
            if (HASBIAS) {
                float2 bv = *(const float2*)(bias + c0);
                lo.x += bv.x; lo.y += bv.y; hi.x += bv.x; hi.y += bv.y;
            }
            *(float2*)(C + (long)r0 * N + c0)       = lo;
            *(float2*)(C + (long)(r0 + 8) * N + c0) = hi;
        }
    }
}

// ---------------------------------------------------------------------------
// (B,T,S,D) -> (B,S,T,D) permute  (verbatim round-2)
// ---------------------------------------------------------------------------
__global__ void transpose_k(const float* __restrict__ x, float* __restrict__ xp)
{
    long idx = (long)blockIdx.x * blockDim.x + threadIdx.x;
    int d = idx & (D_ - 1);
    long r = idx >> 9;
    int t = (int)(r & (T_ - 1));
    long r2 = r >> 4;
    int s = (int)(r2 & (S_ - 1));
    int b = (int)(r2 >> 9);
    xp[idx] = x[(((long)(b * T_ + t)) * S_ + s) * D_ + d];
}

// ---------------------------------------------------------------------------
// Attention core per (token, head)  (verbatim round-2)
// ---------------------------------------------------------------------------
__global__ __launch_bounds__(128)
void attn_core_k(const float* __restrict__ q, const float* __restrict__ k,
                 const float* __restrict__ v, float* __restrict__ av)
{
    __shared__ float qs[16][128], ks[16][128], vsm[16][128];
    __shared__ float sc[16][17];
    const int tid = threadIdx.x;
    const long token = blockIdx.x >> 2;
    const int h = blockIdx.x & 3;
    const long base = token * 16 * 512 + h * 128;

#pragma unroll
    for (int t = 0; t < 16; ++t) {
        qs[t][tid]  = q[base + (long)t * 512 + tid];
        ks[t][tid]  = k[base + (long)t * 512 + tid];
        vsm[t][tid] = v[base + (long)t * 512 + tid];
    }
    __syncthreads();

    for (int p = tid; p < 256; p += 128) {
        int t = p >> 4, u = p & 15;
        float acc = 0.0f;
#pragma unroll
        for (int d = 0; d < 128; ++d) acc += qs[t][d] * ks[u][d];
        sc[t][u] = acc / 11.3137084989847612f;   // / sqrt(128)
    }
    __syncthreads();

    if (tid < 16) {
        int t = tid;
        float mx = sc[t][0];
#pragma unroll
        for (int u = 1; u < 16; ++u) mx = fmaxf(mx, sc[t][u]);
        float e[16], sum = 0.0f;
#pragma unroll
        for (int u = 0; u < 16; ++u) { e[u] = expf(sc[t][u] - mx); sum += e[u]; }
#pragma unroll
        for (int u = 0; u < 16; ++u) sc[t][u] = e[u] / sum;
    }
    __syncthreads();

#pragma unroll
    for (int t = 0; t < 16; ++t) {
        float acc = 0.0f;
#pragma unroll
        for (int u = 0; u < 16; ++u) acc += sc[t][u] * vsm[u][tid];
        av[base + (long)t * 512 + tid] = acc;
    }
}

// ---------------------------------------------------------------------------
// h = x + permute(out_attn); hmean = mean_t(h)   (verbatim round-2)
// ---------------------------------------------------------------------------
__global__ void finalize_k(const float* __restrict__ xspk, const float* __restrict__ oat,
                           float* __restrict__ hout, float* __restrict__ hmean)
{
    int idx = blockIdx.x * blockDim.x + threadIdx.x;  // over NTOK*D_
    int d   = idx & (D_ - 1);
    int tok = idx >> 9;
    int b   = tok >> 9;
    int s   = tok & (S_ - 1);
    float sum = 0.0f;
#pragma unroll
    for (int t = 0; t < 16; ++t) {
        long hidx = (((long)(b * T_ + t)) * S_ + s) * D_ + d;
        float val = xspk[hidx] + oat[(((long)tok) * T_ + t) * D_ + d];
        hout[hidx] = val;
        sum += val;
    }
    hmean[(long)tok * D_ + d] = sum * (1.0f / 16.0f);
}

// ---------------------------------------------------------------------------
// host
// ---------------------------------------------------------------------------
extern "C" void kernel_launch(void* const* d_in, const int* in_sizes, int n_in,
                              void* d_out, int out_size)
{
    const int*   ids  = (const int*)d_in[0];
    const float* emb  = (const float*)d_in[1];
    const float* scal = (const float*)d_in[2];
    const float* Aall = (const float*)d_in[3];
    const float* Ball = (const float*)d_in[4];
    const float* Call = (const float*)d_in[5];
    const float* Dall = (const float*)d_in[6];
    const float* wq = (const float*)d_in[7];   const float* bq = (const float*)d_in[8];
    const float* wk = (const float*)d_in[9];   const float* bk = (const float*)d_in[10];
    const float* wv = (const float*)d_in[11];  const float* bv = (const float*)d_in[12];
    const float* wo = (const float*)d_in[13];  const float* bo = (const float*)d_in[14];
    const float* wout = (const float*)d_in[15];const float* bout = (const float*)d_in[16];
    float* out = (float*)d_out;

    float* arena = nullptr;
    cudaGetSymbolAddress((void**)&arena, g_arena);

    float* spk0   = arena + OFF_SPK0;
    float* spk1   = arena + OFF_SPK1;
    float* xp     = arena + OFF_XP;
    float* qb     = arena + OFF_Q;
    float* kb     = arena + OFF_K;
    float* vb     = arena + OFF_V;
    float* hstate = arena + OFF_HST;
    float* vs     = arena + OFF_VS;
    float* vo     = arena + OFF_VO;
    float* ou     = arena + OFF_OU;
    float* hmean  = arena + OFF_HM;
    float* thr_s  = arena + OFF_THRS;
    float* thr_o  = arena + OFF_THRO;
    int*   cnt_s  = (int*)(arena + OFF_CNTS);
    int*   cnt_o  = (int*)(arena + OFF_CNTO);
    int*   flags  = (int*)(arena + OFF_FLG);

    // -------- encode (verbatim round-2) --------
    cudaMemsetAsync(spk0, 0, SPK * sizeof(float));
    cudaMemsetAsync(flags, 0, 48 * sizeof(int));
    encode_k<<<(NTOK * D_) / 256, 256>>>(ids, emb, scal, spk0, flags);

    // -------- SSM layers (verbatim round-2) --------
    for (int l = 0; l < 2; ++l) {
        const float* Al = Aall + (long)l * DS_ * DS_;
        const float* Bl = Ball + (long)l * DS_ * D_;
        const float* Cl = Call + (long)l * D_ * DS_;
        const float* Dl = Dall + (long)l * D_ * D_;
        float* xin  = l ? spk1 : spk0;
        float* xout = l ? spk0 : spk1;
        int* fin  = flags + (l ? 16 : 0);
        int* fout = flags + (l ? 32 : 16);

        cudaMemsetAsync(xout, 0, SPK * sizeof(float));
        cudaMemsetAsync(hstate, 0,
                        ((long)NTOK * DS_ * 2 + (long)NTOK * D_) * sizeof(float));
        init_thr_k<<<1, 512>>>(thr_s, thr_o);

        for (int t = 0; t < T_; ++t) {
            cudaMemsetAsync(cnt_s, 0, (64 + 512) * sizeof(int));
            step_state_k<<<NTOK / 16, 64>>>(xin, t, Al, Bl, hstate, vs,
                                            thr_s, cnt_s, fin + t);
            thr_update_k<<<1, 64>>>(thr_s, cnt_s, 64, nullptr);
            // ou = hstate @ Cl^T  (K=64)
            sgemm_k<false, false><<<dim3(4, 16), 256>>>(
                hstate, Cl, nullptr, ou, NTOK, D_, DS_,
                (long)NTOK * DS_, (long)DS_, 0L, NTOK, fin + t);
            // ou += x_t @ Dl^T  (K=512, time-sliced A layout)
            sgemm_k<true, false><<<dim3(4, 16), 256>>>(
                xin, Dl, nullptr, ou, NTOK, D_, D_,
                (long)T_ * S_ * D_, (long)D_, (long)t * S_ * D_, S_, fin + t);
            out_lif_k<<<NTOK / 32, 512>>>(ou, vo, thr_o, xout, t,
                                          cnt_o, fout + t, fin + t);
            thr_update_k<<<2, 256>>>(thr_o, cnt_o, 512, fin + t);
        }
    }
    // after 2 layers: attention input = spk0 (B,T,S,D)

    // -------- attention (tensor cores) --------
    transpose_k<<<(int)(SPK / 256), 256>>>(spk0, xp);
    const int MA = B_ * S_ * T_;  // 32768
    // q/k/v: A = binary spikes, exact in tf32 -> MODE 1 (2 mma)
    gemm_tf32_k<1, true><<<dim3(D_ / 128, MA / 128), 256>>>(
        xp, wq, bq, qb, MA, D_, D_);
    gemm_tf32_k<1, true><<<dim3(D_ / 128, MA / 128), 256>>>(
        xp, wk, bk, kb, MA, D_, D_);
    gemm_tf32_k<1, true><<<dim3(D_ / 128, MA / 128), 256>>>(
        xp, wv, bv, vb, MA, D_, D_);
    attn_core_k<<<NTOK * 4, 128>>>(qb, kb, vb, spk1);           // av -> spk1
    // o-projection: full 4-mma split-split (fp32-equivalent)
    gemm_tf32_k<4, true><<<dim3(D_ / 128, MA / 128), 256>>>(
        spk1, wo, bo, kb, MA, D_, D_);                          // -> kb

    // -------- residual + mean + outputs --------
    float* hout = ((long)out_size >= LOGITS_SZ + H_SZ) ? (out + LOGITS_SZ) : xp;
    finalize_k<<<(NTOK * D_) / 256, 256>>>(spk0, kb, hout, hmean);

    // logits: full 4-mma split-split (fp32-equivalent)
    gemm_tf32_k<4, true><<<dim3(V_ / 128, NTOK / 128), 256>>>(
        hmean, wout, bout, out, NTOK, V_, D_);
}

// round 8
// speedup vs baseline: 1.1425x; 1.1030x over previous
#include <cuda_runtime.h>
#include <cuda_bf16.h>
#include <math.h>

// ---------------------------------------------------------------------------
// Problem constants
// ---------------------------------------------------------------------------
#define B_    4
#define S_    512
#define T_    16
#define D_    512
#define DS_   64
#define V_    32000
#define NTOK  2048              // B_*S_
#define NROWS 32768             // B_*T_*S_
#define DECAY 0.60653065971263342f   // exp(-1/2)

static const long SPK       = (long)NROWS * D_;   // 16,777,216 floats
static const long LOGITS_SZ = (long)NTOK * V_;    // 65,536,000 floats
static const long H_SZ      = SPK;

// arena offsets (floats)
static const long OFF_SPK0 = 0;
static const long OFF_SPK1 = SPK;
static const long OFF_XP   = 2 * SPK;
static const long OFF_Q    = 3 * SPK;             // doubles as OU (32768x512)
static const long OFF_K    = 4 * SPK;
static const long OFF_V    = 5 * SPK;
static const long OFF_HST  = 6 * SPK;                       // 2048 x 64
static const long OFF_VS   = OFF_HST + (long)NTOK * DS_;    // 2048 x 64
static const long OFF_VO   = OFF_VS  + (long)NTOK * DS_;    // 2048 x 512
static const long OFF_HM   = OFF_VO  + (long)NTOK * D_;     // 2048 x 512
static const long OFF_THRS = OFF_HM  + (long)NTOK * D_;     // 64
static const long OFF_THRO = OFF_THRS + 64;                 // 512
static const long OFF_CNT  = OFF_THRO + 512;      // ints: 16*64 (s) + 16*512 (o)
static const long CNT_INTS = 16 * 64 + 16 * 512;  // 9216
static const long OFF_FLG  = OFF_CNT + CNT_INTS;  // 48 ints
static const long OFF_HALL = OFF_FLG + 64;        // 32768 x 64
static const long ARENA_TOTAL = OFF_HALL + (long)NROWS * DS_;

__device__ __align__(256) float g_arena[ARENA_TOTAL];

// ===========================================================================
// SSM SECTION -- arithmetic is BITWISE-IDENTICAL to the round-2/7 passing
// kernels. Only thread assignment / launch structure changed; every
// (token,channel) FP chain keeps its exact sequential order.
// ===========================================================================

__global__ void encode_k(const int* __restrict__ ids, const float* __restrict__ emb,
                         const float* __restrict__ scaling,
                         float* __restrict__ spk, int* __restrict__ flag)
{
    int idx = blockIdx.x * blockDim.x + threadIdx.x;   // over NTOK*D_
    int d   = idx & (D_ - 1);
    int tok = idx >> 9;
    int b   = tok >> 9;
    int s   = tok & (S_ - 1);
    float e = emb[(long)ids[tok] * D_ + d];
    float a = 1.0f / (1.0f + expf(-(*scaling) * e));
    float tr = rintf(10.0f * (1.0f - a));
    int ti = (int)tr;
    if (ti < 0) ti = 0;
    if (ti > T_ - 1) ti = T_ - 1;
    spk[(((long)(b * T_ + ti)) * S_ + s) * D_ + d] = 1.0f;
    flag[ti] = 1;
}

// State step: per (token,m) chain acc over n (h@A) then d (x@B), sequential --
// identical expressions to round-2's step_state_k. 256 threads: 4 threads per
// channel m, each owning 4 token-chains. Adds H_all store (pure store).
__global__ __launch_bounds__(256)
void step_state_k(const float* __restrict__ spk_in, int t,
                  const float* __restrict__ Amat, const float* __restrict__ Bmat,
                  float* __restrict__ hstate, float* __restrict__ vs,
                  const float* __restrict__ thr_s, int* __restrict__ cnt,
                  const int* __restrict__ flag, float* __restrict__ Hall)
{
    __shared__ float xs[16][D_];
    __shared__ float hs[16][DS_];
    const int tid  = threadIdx.x;
    const int m    = tid & 63;
    const int lt   = tid >> 6;          // 0..3
    const int tok0 = blockIdx.x * 16;
    const int active = flag[0];

    for (int i = tid; i < 16 * DS_; i += 256) {
        int tk = i >> 6, c = i & 63;
        hs[tk][c] = hstate[(long)(tok0 + tk) * DS_ + c];
    }
    if (active) {
        for (int i = tid; i < 16 * D_; i += 256) {
            int tk = i >> 9, d = i & (D_ - 1);
            int tok = tok0 + tk;
            int b = tok >> 9, s = tok & (S_ - 1);
            xs[tk][d] = spk_in[(((long)(b * T_ + t)) * S_ + s) * D_ + d];
        }
    }
    __syncthreads();

    float acc[4];
#pragma unroll
    for (int j = 0; j < 4; ++j) acc[j] = 0.0f;

    for (int n = 0; n < DS_; ++n) {
        float a = Amat[m * DS_ + n];
#pragma unroll
        for (int j = 0; j < 4; ++j) acc[j] += hs[lt + 4 * j][n] * a;
    }
    if (active) {
        for (int d = 0; d < D_; ++d) {
            float bv = Bmat[m * D_ + d];
#pragma unroll
            for (int j = 0; j < 4; ++j) acc[j] += xs[lt + 4 * j][d] * bv;
        }
    }

    const float thr = thr_s[m];
    int c = 0;
#pragma unroll
    for (int j = 0; j < 4; ++j) {
        int tk = lt + 4 * j;
        int tok = tok0 + tk;
        long idx = (long)tok * DS_ + m;
        float v = vs[idx] * DECAY + acc[j];
        float sp = (v - thr >= 0.0f) ? 1.0f : 0.0f;
        v *= (1.0f - sp);
        vs[idx] = v;
        hstate[idx] = sp;
        int b = tok >> 9, s = tok & (S_ - 1);
        Hall[(((long)(b * T_ + t)) * S_ + s) * DS_ + m] = sp;
        c += (int)sp;
    }
    if (c) atomicAdd(&cnt[m], c);
}

__global__ void thr_update_k(float* __restrict__ thr, const int* __restrict__ cnt,
                             int n, const int* __restrict__ flag)
{
    if (flag && flag[0] == 0) return;
    int i = blockIdx.x * blockDim.x + threadIdx.x;
    if (i < n) {
        float mean = (float)cnt[i] * (1.0f / 2048.0f);
        thr[i] += 0.1f * (mean - 0.1f);
    }
}

// Output LIF step t reading hoisted OU rows (values identical to per-step ou).
__global__ __launch_bounds__(512)
void out_lif_k(const float* __restrict__ OU, int t, float* __restrict__ vo,
               const float* __restrict__ thr_o, float* __restrict__ spk_out,
               int* __restrict__ cnt, int* __restrict__ flagOut,
               const int* __restrict__ flagIn)
{
    if (flagIn[0] == 0) return;
    const int e    = threadIdx.x;
    const int tok0 = blockIdx.x * 32;
    const float thr = thr_o[e];
    int c = 0;
    for (int tk = 0; tk < 32; ++tk) {
        int tok = tok0 + tk;
        int b = tok >> 9, s = tok & (S_ - 1);
        long rowD = (((long)(b * T_ + t)) * S_ + s) * D_;
        long vi = (long)tok * D_ + e;
        float v = vo[vi] * DECAY + OU[rowD + e];
        float sp = (v - thr >= 0.0f) ? 1.0f : 0.0f;
        v *= (1.0f - sp);
        vo[vi] = v;
        spk_out[rowD + e] = sp;
        c += (int)sp;
    }
    if (c) { atomicAdd(&cnt[e], c); flagOut[0] = 1; }
}

__global__ void init_thr_k(float* __restrict__ thr_s, float* __restrict__ thr_o)
{
    int i = threadIdx.x;
    if (i < 64) thr_s[i] = 1.0f;
    thr_o[i] = 1.0f;
}

// fp32 SGEMM -- verbatim round-2 kernel (k-sequential chain per output row;
// grid/M-independent, so hoisted big-M launches are bitwise identical).
template<bool ACC, bool HASBIAS>
__global__ __launch_bounds__(256)
void sgemm_k(const float* __restrict__ A, const float* __restrict__ W,
             const float* __restrict__ bias, float* __restrict__ C,
             int M, int N, int K,
             long aOuter, long aInner, long aConst, int aSdiv,
             const int* __restrict__ flag)
{
    if (flag && flag[0] == 0) return;
    __shared__ float As[8][128];
    __shared__ float Bs[8][128];
    const int tid = threadIdx.x;
    const int bx = blockIdx.x, by = blockIdx.y;
    const int tx = tid & 15, ty = tid >> 4;

    const int lrow = tid >> 1;
    const int lk4  = (tid & 1) * 4;

    const int arow = by * 128 + lrow;
    const long aoff = (long)(arow / aSdiv) * aOuter + (long)(arow % aSdiv) * aInner + aConst;
    const float* Aptr = A + aoff + lk4;
    const float* Wptr = W + (long)(bx * 128 + lrow) * K + lk4;

    float acc[8][8];
#pragma unroll
    for (int i = 0; i < 8; ++i)
#pragma unroll
        for (int j = 0; j < 8; ++j) acc[i][j] = 0.0f;

    for (int k0 = 0; k0 < K; k0 += 8) {
        float4 av = *(const float4*)(Aptr + k0);
        float4 wv = *(const float4*)(Wptr + k0);
        As[lk4 + 0][lrow] = av.x; As[lk4 + 1][lrow] = av.y;
        As[lk4 + 2][lrow] = av.z; As[lk4 + 3][lrow] = av.w;
        Bs[lk4 + 0][lrow] = wv.x; Bs[lk4 + 1][lrow] = wv.y;
        Bs[lk4 + 2][lrow] = wv.z; Bs[lk4 + 3][lrow] = wv.w;
        __syncthreads();
#pragma unroll
        for (int k = 0; k < 8; ++k) {
            float ar[8], br[8];
            *(float4*)&ar[0] = *(const float4*)&As[k][ty * 4];
            *(float4*)&ar[4] = *(const float4*)&As[k][64 + ty * 4];
            *(float4*)&br[0] = *(const float4*)&Bs[k][tx * 4];
            *(float4*)&br[4] = *(const float4*)&Bs[k][64 + tx * 4];
#pragma unroll
            for (int i = 0; i < 8; ++i)
#pragma unroll
                for (int j = 0; j < 8; ++j)
                    acc[i][j] += ar[i] * br[j];
        }
        __syncthreads();
    }

#pragma unroll
    for (int i = 0; i < 8; ++i) {
        int row = by * 128 + ((i < 4) ? (ty * 4 + i) : (64 + ty * 4 + (i - 4)));
        float* crow = C + (long)row * N + bx * 128;
#pragma unroll
        for (int half = 0; half < 2; ++half) {
            int colbase = half * 64 + tx * 4;
            float4 r;
            r.x = acc[i][half * 4 + 0]; r.y = acc[i][half * 4 + 1];
            r.z = acc[i][half * 4 + 2]; r.w = acc[i][half * 4 + 3];
            if (HASBIAS) {
                float4 bv = *(const float4*)(bias + bx * 128 + colbase);
                r.x += bv.x; r.y += bv.y; r.z += bv.z; r.w += bv.w;
            }
            if (ACC) {
                float4 ov = *(const float4*)(crow + colbase);
                r.x += ov.x; r.y += ov.y; r.z += ov.z; r.w += ov.w;
            }
            *(float4*)(crow + colbase) = r;
        }
    }
}

// ===========================================================================
// TENSOR-CORE SECTION -- tf32 split GEMMs (smooth paths only).
// MODE 1: A exact (binary), W=hi+lo       (2 mma)
// MODE 2: A=hi+lo, W=hi+lo, drop lo*lo    (3 mma)
// MODE 4: full Markidis                   (4 mma)
// ===========================================================================
__device__ __forceinline__ unsigned f2tf(float x) {
    unsigned u;
    asm("cvt.rna.tf32.f32 %0, %1;" : "=r"(u) : "f"(x));
    return u;
}

__device__ __forceinline__ void mma8(float* c, const unsigned* a, const unsigned* b) {
    asm volatile(
        "mma.sync.aligned.m16n8k8.row.col.f32.tf32.tf32.f32 "
        "{%0,%1,%2,%3},{%4,%5,%6,%7},{%8,%9},{%0,%1,%2,%3};"
        : "+f"(c[0]), "+f"(c[1]), "+f"(c[2]), "+f"(c[3])
        : "r"(a[0]), "r"(a[1]), "r"(a[2]), "r"(a[3]), "r"(b[0]), "r"(b[1]));
}

template<int MODE, bool HASBIAS>
__global__ __launch_bounds__(256)
void gemm_tf32_k(const float* __restrict__ A, const float* __restrict__ W,
                 const float* __restrict__ bias, float* __restrict__ C,
                 int M, int N, int K)
{
    constexpr int BM = 128, BN = 128, BK = 16;
    constexpr int MT = 4, NT = 4;
    __shared__ float As[BK][BM + 8];
    __shared__ float Bs[BK][BN + 8];

    const int tid  = threadIdx.x;
    const int warp = tid >> 5, lane = tid & 31;
    const int wm = warp & 1, wn = warp >> 1;
    const int mW = wm * 64, nW = wn * 32;
    const int g = lane >> 2, q = lane & 3;
    const int bx = blockIdx.x, by = blockIdx.y;

    const int lr = tid >> 1;
    const int lk = (tid & 1) * 8;
    const float* Ag = A + (long)(by * BM + lr) * K + lk;
    const float* Wg = W + (long)(bx * BN + lr) * K + lk;

    float acc[MT][NT][4];
#pragma unroll
    for (int i = 0; i < MT; ++i)
#pragma unroll
        for (int j = 0; j < NT; ++j)
#pragma unroll
            for (int r = 0; r < 4; ++r) acc[i][j][r] = 0.0f;

    for (int k0 = 0; k0 < K; k0 += BK) {
        float4 a0 = *(const float4*)(Ag + k0);
        float4 a1 = *(const float4*)(Ag + k0 + 4);
        As[lk + 0][lr] = a0.x; As[lk + 1][lr] = a0.y;
        As[lk + 2][lr] = a0.z; As[lk + 3][lr] = a0.w;
        As[lk + 4][lr] = a1.x; As[lk + 5][lr] = a1.y;
        As[lk + 6][lr] = a1.z; As[lk + 7][lr] = a1.w;
        float4 w0 = *(const float4*)(Wg + k0);
        float4 w1 = *(const float4*)(Wg + k0 + 4);
        Bs[lk + 0][lr] = w0.x; Bs[lk + 1][lr] = w0.y;
        Bs[lk + 2][lr] = w0.z; Bs[lk + 3][lr] = w0.w;
        Bs[lk + 4][lr] = w1.x; Bs[lk + 5][lr] = w1.y;
        Bs[lk + 6][lr] = w1.z; Bs[lk + 7][lr] = w1.w;
        __syncthreads();

#pragma unroll
        for (int ks = 0; ks < BK; ks += 8) {
            unsigned ahi[MT][4], alo[MT][4];
            unsigned bhi[NT][2], blo[NT][2];
#pragma unroll
            for (int i = 0; i < MT; ++i) {
                int m = mW + i * 16 + g;
                float x0 = As[ks + q][m];
                float x1 = As[ks + q][m + 8];
                float x2 = As[ks + 4 + q][m];
                float x3 = As[ks + 4 + q][m + 8];
                ahi[i][0] = f2tf(x0); ahi[i][1] = f2tf(x1);
                ahi[i][2] = f2tf(x2); ahi[i][3] = f2tf(x3);
                if (MODE >= 2) {
                    alo[i][0] = f2tf(x0 - __uint_as_float(ahi[i][0]));
                    alo[i][1] = f2tf(x1 - __uint_as_float(ahi[i][1]));
                    alo[i][2] = f2tf(x2 - __uint_as_float(ahi[i][2]));
                    alo[i][3] = f2tf(x3 - __uint_as_float(ahi[i][3]));
                }
            }
#pragma unroll
            for (int j = 0; j < NT; ++j) {
                int n = nW + j * 8 + g;
                float y0 = Bs[ks + q][n];
                float y1 = Bs[ks + 4 + q][n];
                bhi[j][0] = f2tf(y0); bhi[j][1] = f2tf(y1);
                blo[j][0] = f2tf(y0 - __uint_as_float(bhi[j][0]));
                blo[j][1] = f2tf(y1 - __uint_as_float(bhi[j][1]));
            }
#pragma unroll
            for (int i = 0; i < MT; ++i)
#pragma unroll
                for (int j = 0; j < NT; ++j) {
                    if (MODE == 4) mma8(acc[i][j], alo[i], blo[j]);
                    if (MODE >= 2) mma8(acc[i][j], alo[i], bhi[j]);
                    mma8(acc[i][j], ahi[i], blo[j]);
                    mma8(acc[i][j], ahi[i], bhi[j]);
                }
        }
        __syncthreads();
    }

#pragma unroll
    for (int i = 0; i < MT; ++i) {
        int r0 = by * BM + mW + i * 16 + g;
#pragma unroll
        for (int j = 0; j < NT; ++j) {
            int c0 = bx * BN + nW + j * 8 + q * 2;
            float2 lo; lo.x = acc[i][j][0]; lo.y = acc[i][j][1];
            float2 hi; hi.x = acc[i][j][2]; hi.y = acc[i][j][3];
            if (HASBIAS) {
                float2 bv = *(const float2*)(bias + c0);
                lo.x += bv.x; lo.y += bv.y; hi.x += bv.x; hi.y += bv.y;
            }
            *(float2*)(C + (long)r0 * N + c0)       = lo;
            *(float2*)(C + (long)(r0 + 8) * N + c0) = hi;
        }
    }
}

// ---------------------------------------------------------------------------
// (B,T,S,D) -> (B,S,T,D) permute
// ---------------------------------------------------------------------------
__global__ void transpose_k(const float* __restrict__ x, float* __restrict__ xp)
{
    long idx = (long)blockIdx.x * blockDim.x + threadIdx.x;
    int d = idx & (D_ - 1);
    long r = idx >> 9;
    int t = (int)(r & (T_ - 1));
    long r2 = r >> 4;
    int s = (int)(r2 & (S_ - 1));
    int b = (int)(r2 >> 9);
    xp[idx] = x[(((long)(b * T_ + t)) * S_ + s) * D_ + d];
}

// ---------------------------------------------------------------------------
// Attention core per (token, head)
// ---------------------------------------------------------------------------
__global__ __launch_bounds__(128)
void attn_core_k(const float* __restrict__ q, const float* __restrict__ k,
                 const float* __restrict__ v, float* __restrict__ av)
{
    __shared__ float qs[16][128], ks[16][128], vsm[16][128];
    __shared__ float sc[16][17];
    const int tid = threadIdx.x;
    const long token = blockIdx.x >> 2;
    const int h = blockIdx.x & 3;
    const long base = token * 16 * 512 + h * 128;

#pragma unroll
    for (int t = 0; t < 16; ++t) {
        qs[t][tid]  = q[base + (long)t * 512 + tid];
        ks[t][tid]  = k[base + (long)t * 512 + tid];
        vsm[t][tid] = v[base + (long)t * 512 + tid];
    }
    __syncthreads();

    for (int p = tid; p < 256; p += 128) {
        int t = p >> 4, u = p & 15;
        float acc = 0.0f;
#pragma unroll
        for (int d = 0; d < 128; ++d) acc += qs[t][d] * ks[u][d];
        sc[t][u] = acc / 11.3137084989847612f;   // / sqrt(128)
    }
    __syncthreads();

    if (tid < 16) {
        int t = tid;
        float mx = sc[t][0];
#pragma unroll
        for (int u = 1; u < 16; ++u) mx = fmaxf(mx, sc[t][u]);
        float e[16], sum = 0.0f;
#pragma unroll
        for (int u = 0; u < 16; ++u) { e[u] = expf(sc[t][u] - mx); sum += e[u]; }
#pragma unroll
        for (int u = 0; u < 16; ++u) sc[t][u] = e[u] / sum;
    }
    __syncthreads();

#pragma unroll
    for (int t = 0; t < 16; ++t) {
        float acc = 0.0f;
#pragma unroll
        for (int u = 0; u < 16; ++u) acc += sc[t][u] * vsm[u][tid];
        av[base + (long)t * 512 + tid] = acc;
    }
}

// ---------------------------------------------------------------------------
// h = x + permute(out_attn); hmean = mean_t(h)
// ---------------------------------------------------------------------------
__global__ void finalize_k(const float* __restrict__ xspk, const float* __restrict__ oat,
                           float* __restrict__ hout, float* __restrict__ hmean)
{
    int idx = blockIdx.x * blockDim.x + threadIdx.x;  // over NTOK*D_
    int d   = idx & (D_ - 1);
    int tok = idx >> 9;
    int b   = tok >> 9;
    int s   = tok & (S_ - 1);
    float sum = 0.0f;
#pragma unroll
    for (int t = 0; t < 16; ++t) {
        long hidx = (((long)(b * T_ + t)) * S_ + s) * D_ + d;
        float val = xspk[hidx] + oat[(((long)tok) * T_ + t) * D_ + d];
        hout[hidx] = val;
        sum += val;
    }
    hmean[(long)tok * D_ + d] = sum * (1.0f / 16.0f);
}

// ---------------------------------------------------------------------------
// host
// ---------------------------------------------------------------------------
extern "C" void kernel_launch(void* const* d_in, const int* in_sizes, int n_in,
                              void* d_out, int out_size)
{
    const int*   ids  = (const int*)d_in[0];
    const float* emb  = (const float*)d_in[1];
    const float* scal = (const float*)d_in[2];
    const float* Aall = (const float*)d_in[3];
    const float* Ball = (const float*)d_in[4];
    const float* Call = (const float*)d_in[5];
    const float* Dall = (const float*)d_in[6];
    const float* wq = (const float*)d_in[7];   const float* bq = (const float*)d_in[8];
    const float* wk = (const float*)d_in[9];   const float* bk = (const float*)d_in[10];
    const float* wv = (const float*)d_in[11];  const float* bv = (const float*)d_in[12];
    const float* wo = (const float*)d_in[13];  const float* bo = (const float*)d_in[14];
    const float* wout = (const float*)d_in[15];const float* bout = (const float*)d_in[16];
    float* out = (float*)d_out;

    float* arena = nullptr;
    cudaGetSymbolAddress((void**)&arena, g_arena);

    float* spk0   = arena + OFF_SPK0;
    float* spk1   = arena + OFF_SPK1;
    float* xp     = arena + OFF_XP;
    float* qb     = arena + OFF_Q;     // OU during SSM phase
    float* kb     = arena + OFF_K;
    float* vb     = arena + OFF_V;
    float* hstate = arena + OFF_HST;
    float* vs     = arena + OFF_VS;
    float* vo     = arena + OFF_VO;
    float* hmean  = arena + OFF_HM;
    float* thr_s  = arena + OFF_THRS;
    float* thr_o  = arena + OFF_THRO;
    int*   cnt    = (int*)(arena + OFF_CNT);   // [16*64 s][16*512 o]
    int*   flags  = (int*)(arena + OFF_FLG);
    float* Hall   = arena + OFF_HALL;
    float* OU     = qb;

    // -------- encode --------
    cudaMemsetAsync(spk0, 0, SPK * sizeof(float));
    cudaMemsetAsync(flags, 0, 48 * sizeof(int));
    encode_k<<<(NTOK * D_) / 256, 256>>>(ids, emb, scal, spk0, flags);

    // -------- SSM layers --------
    for (int l = 0; l < 2; ++l) {
        const float* Al = Aall + (long)l * DS_ * DS_;
        const float* Bl = Ball + (long)l * DS_ * D_;
        const float* Cl = Call + (long)l * D_ * DS_;
        const float* Dl = Dall + (long)l * D_ * D_;
        float* xin  = l ? spk1 : spk0;
        float* xout = l ? spk0 : spk1;
        int* fin  = flags + (l ? 16 : 0);
        int* fout = flags + (l ? 32 : 16);

        cudaMemsetAsync(xout, 0, SPK * sizeof(float));
        cudaMemsetAsync(hstate, 0,
                        ((long)NTOK * DS_ * 2 + (long)NTOK * D_) * sizeof(float));
        cudaMemsetAsync(cnt, 0, CNT_INTS * sizeof(int));
        init_thr_k<<<1, 512>>>(thr_s, thr_o);

        // state recurrence (sequential in t; thr_s ladder preserved)
        for (int t = 0; t < T_; ++t) {
            step_state_k<<<NTOK / 16, 256>>>(xin, t, Al, Bl, hstate, vs,
                                             thr_s, cnt + t * 64, fin + t, Hall);
            thr_update_k<<<1, 64>>>(thr_s, cnt + t * 64, 64, nullptr);
        }

        // hoisted output-path GEMMs (bitwise == per-step sgemm_k launches)
        // OU = Hall @ C^T  (M=32768, K=64)
        sgemm_k<false, false><<<dim3(4, NROWS / 128), 256>>>(
            Hall, Cl, nullptr, OU, NROWS, D_, DS_,
            (long)NROWS * DS_, (long)DS_, 0L, NROWS, nullptr);
        // OU += X @ D^T  (M=32768, K=512)
        sgemm_k<true, false><<<dim3(4, NROWS / 128), 256>>>(
            xin, Dl, nullptr, OU, NROWS, D_, D_,
            (long)NROWS * D_, (long)D_, 0L, NROWS, nullptr);

        // output LIF ladder (sequential in t for v_o / thr_o)
        for (int t = 0; t < T_; ++t) {
            out_lif_k<<<NTOK / 32, 512>>>(OU, t, vo, thr_o, xout,
                                          cnt + 16 * 64 + t * 512,
                                          fout + t, fin + t);
            thr_update_k<<<2, 256>>>(thr_o, cnt + 16 * 64 + t * 512, 512, fin + t);
        }
    }
    // after 2 layers: attention input = spk0 (B,T,S,D)

    // -------- attention (tensor cores) --------
    transpose_k<<<(int)(SPK / 256), 256>>>(spk0, xp);
    const int MA = NROWS;  // 32768
    // q/k/v: A = binary spikes, exact in tf32 -> MODE 1 (2 mma)
    gemm_tf32_k<1, true><<<dim3(D_ / 128, MA / 128), 256>>>(
        xp, wq, bq, qb, MA, D_, D_);
    gemm_tf32_k<1, true><<<dim3(D_ / 128, MA / 128), 256>>>(
        xp, wk, bk, kb, MA, D_, D_);
    gemm_tf32_k<1, true><<<dim3(D_ / 128, MA / 128), 256>>>(
        xp, wv, bv, vb, MA, D_, D_);
    attn_core_k<<<NTOK * 4, 128>>>(qb, kb, vb, spk1);           // av -> spk1
    // o-projection: 3-mma split-split (err ~2^-22, no Heaviside downstream)
    gemm_tf32_k<2, true><<<dim3(D_ / 128, MA / 128), 256>>>(
        spk1, wo, bo, kb, MA, D_, D_);                          // -> kb

    // -------- residual + mean + outputs --------
    float* hout = ((long)out_size >= LOGITS_SZ + H_SZ) ? (out + LOGITS_SZ) : xp;
    finalize_k<<<(NTOK * D_) / 256, 256>>>(spk0, kb, hout, hmean);

    // logits: 3-mma split-split
    gemm_tf32_k<2, true><<<dim3(V_ / 128, NTOK / 128), 256>>>(
        hmean, wout, bout, out, NTOK, V_, D_);
}

// round 9
// speedup vs baseline: 1.5269x; 1.3364x over previous
#include <cuda_runtime.h>
#include <cuda_bf16.h>
#include <math.h>

// ---------------------------------------------------------------------------
// Problem constants
// ---------------------------------------------------------------------------
#define B_    4
#define S_    512
#define T_    16
#define D_    512
#define DS_   64
#define V_    32000
#define NTOK  2048              // B_*S_
#define NROWS 32768             // B_*T_*S_
#define DECAY 0.60653065971263342f   // exp(-1/2)

static const long SPK       = (long)NROWS * D_;   // 16,777,216 floats
static const long LOGITS_SZ = (long)NTOK * V_;    // 65,536,000 floats
static const long H_SZ      = SPK;

// arena offsets (floats)
static const long OFF_SPK0 = 0;
static const long OFF_SPK1 = SPK;
static const long OFF_XP   = 2 * SPK;
static const long OFF_Q    = 3 * SPK;             // doubles as OU (32768x512)
static const long OFF_K    = 4 * SPK;
static const long OFF_V    = 5 * SPK;
static const long OFF_HST  = 6 * SPK;                       // 2048 x 64
static const long OFF_VS   = OFF_HST + (long)NTOK * DS_;    // 2048 x 64
static const long OFF_VO   = OFF_VS  + (long)NTOK * DS_;    // 2048 x 512
static const long OFF_HM   = OFF_VO  + (long)NTOK * D_;     // 2048 x 512
static const long OFF_CNT  = OFF_HM  + (long)NTOK * D_;     // ints: 16*64
static const long CNT_INTS = 16 * 64;
static const long OFF_FLG  = OFF_CNT + CNT_INTS;            // 48 ints
static const long OFF_HALL = OFF_FLG + 64;                  // 32768 x 64
static const long ARENA_TOTAL = OFF_HALL + (long)NROWS * DS_;

__device__ __align__(256) float g_arena[ARENA_TOTAL];

// ===========================================================================
// SSM SECTION -- LIF arithmetic is BITWISE-IDENTICAL to the R2/R7/R8 passing
// kernels. Threshold replay uses the same float op sequence as the iterative
// thr_update launches it replaces.
// ===========================================================================

__global__ void encode_k(const int* __restrict__ ids, const float* __restrict__ emb,
                         const float* __restrict__ scaling,
                         float* __restrict__ spk, int* __restrict__ flag)
{
    int idx = blockIdx.x * blockDim.x + threadIdx.x;   // over NTOK*D_
    int d   = idx & (D_ - 1);
    int tok = idx >> 9;
    int b   = tok >> 9;
    int s   = tok & (S_ - 1);
    float e = emb[(long)ids[tok] * D_ + d];
    float a = 1.0f / (1.0f + expf(-(*scaling) * e));
    float tr = rintf(10.0f * (1.0f - a));
    int ti = (int)tr;
    if (ti < 0) ti = 0;
    if (ti > T_ - 1) ti = T_ - 1;
    spk[(((long)(b * T_ + ti)) * S_ + s) * D_ + d] = 1.0f;
    flag[ti] = 1;
}

// State step with in-kernel thr_s replay (bitwise == the iterative updates).
__global__ __launch_bounds__(256)
void step_state_k(const float* __restrict__ spk_in, int t,
                  const float* __restrict__ Amat, const float* __restrict__ Bmat,
                  float* __restrict__ hstate, float* __restrict__ vs,
                  int* __restrict__ cnt, const int* __restrict__ flag,
                  float* __restrict__ Hall)
{
    __shared__ float xs[16][D_];
    __shared__ float hs[16][DS_];
    const int tid  = threadIdx.x;
    const int m    = tid & 63;
    const int lt   = tid >> 6;          // 0..3
    const int tok0 = blockIdx.x * 16;
    const int active = flag[0];

    for (int i = tid; i < 16 * DS_; i += 256) {
        int tk = i >> 6, c = i & 63;
        hs[tk][c] = hstate[(long)(tok0 + tk) * DS_ + c];
    }
    if (active) {
        for (int i = tid; i < 16 * D_; i += 256) {
            int tk = i >> 9, d = i & (D_ - 1);
            int tok = tok0 + tk;
            int b = tok >> 9, s = tok & (S_ - 1);
            xs[tk][d] = spk_in[(((long)(b * T_ + t)) * S_ + s) * D_ + d];
        }
    }
    // thr_s replay: identical op sequence to the per-step thr_update launches
    float thr = 1.0f;
    for (int tp = 0; tp < t; ++tp) {
        float mean = (float)cnt[tp * 64 + m] * (1.0f / 2048.0f);
        thr += 0.1f * (mean - 0.1f);
    }
    __syncthreads();

    float acc[4];
#pragma unroll
    for (int j = 0; j < 4; ++j) acc[j] = 0.0f;

    for (int n = 0; n < DS_; ++n) {
        float a = Amat[m * DS_ + n];
#pragma unroll
        for (int j = 0; j < 4; ++j) acc[j] += hs[lt + 4 * j][n] * a;
    }
    if (active) {
        for (int d = 0; d < D_; ++d) {
            float bv = Bmat[m * D_ + d];
#pragma unroll
            for (int j = 0; j < 4; ++j) acc[j] += xs[lt + 4 * j][d] * bv;
        }
    }

    int c = 0;
#pragma unroll
    for (int j = 0; j < 4; ++j) {
        int tk = lt + 4 * j;
        int tok = tok0 + tk;
        long idx = (long)tok * DS_ + m;
        float v = vs[idx] * DECAY + acc[j];
        float sp = (v - thr >= 0.0f) ? 1.0f : 0.0f;
        v *= (1.0f - sp);
        vs[idx] = v;
        hstate[idx] = sp;
        int b = tok >> 9, s = tok & (S_ - 1);
        Hall[(((long)(b * T_ + t)) * S_ + s) * DS_ + m] = sp;
        c += (int)sp;
    }
    if (c) atomicAdd(&cnt[t * 64 + m], c);
}

// Fused output LIF over all 16 steps. Block = 4 channels x all 2048 tokens;
// v in registers; thr sequential in-register (same count -> mean -> thr float
// ops as the out_lif + thr_update pair). Writes zeros on inactive steps.
__global__ __launch_bounds__(256)
void out_fused_k(const float* __restrict__ OU, const int* __restrict__ flags,
                 float* __restrict__ spk_out, int* __restrict__ flags_next)
{
    const int tid = threadIdx.x;
    const int el  = tid & 3;
    const int e   = blockIdx.x * 4 + el;
    const int ts  = tid >> 2;                 // 0..63
    __shared__ int scnt[4];

    float v[32];
#pragma unroll
    for (int j = 0; j < 32; ++j) v[j] = 0.0f;
    float thr = 1.0f;

    for (int t = 0; t < T_; ++t) {
        int act = flags[t];
        if (tid < 4) scnt[tid] = 0;
        __syncthreads();
        if (act) {
            int c = 0;
#pragma unroll
            for (int j = 0; j < 32; ++j) {
                int tok = ts + 64 * j;
                int b = tok >> 9, s = tok & (S_ - 1);
                long row = (long)b * (T_ * S_) + (long)t * S_ + s;
                float vv = v[j] * DECAY + OU[row * D_ + e];
                float sp = (vv - thr >= 0.0f) ? 1.0f : 0.0f;
                v[j] = vv * (1.0f - sp);
                spk_out[row * D_ + e] = sp;
                c += (int)sp;
            }
            if (c) atomicAdd(&scnt[el], c);
        } else {
#pragma unroll
            for (int j = 0; j < 32; ++j) {
                int tok = ts + 64 * j;
                int b = tok >> 9, s = tok & (S_ - 1);
                long row = (long)b * (T_ * S_) + (long)t * S_ + s;
                spk_out[row * D_ + e] = 0.0f;
            }
        }
        __syncthreads();
        if (act) {
            int cc = scnt[el];
            float mean = (float)cc * (1.0f / 2048.0f);
            thr += 0.1f * (mean - 0.1f);
            if (tid == 0 && (scnt[0] | scnt[1] | scnt[2] | scnt[3]))
                flags_next[t] = 1;
        }
        __syncthreads();
    }
}

// fp32 SGEMM -- verbatim round-2 kernel (k-sequential chain per output row).
template<bool ACC, bool HASBIAS>
__global__ __launch_bounds__(256)
void sgemm_k(const float* __restrict__ A, const float* __restrict__ W,
             const float* __restrict__ bias, float* __restrict__ C,
             int M, int N, int K,
             long aOuter, long aInner, long aConst, int aSdiv,
             const int* __restrict__ flag)
{
    if (flag && flag[0] == 0) return;
    __shared__ float As[8][128];
    __shared__ float Bs[8][128];
    const int tid = threadIdx.x;
    const int bx = blockIdx.x, by = blockIdx.y;
    const int tx = tid & 15, ty = tid >> 4;

    const int lrow = tid >> 1;
    const int lk4  = (tid & 1) * 4;

    const int arow = by * 128 + lrow;
    const long aoff = (long)(arow / aSdiv) * aOuter + (long)(arow % aSdiv) * aInner + aConst;
    const float* Aptr = A + aoff + lk4;
    const float* Wptr = W + (long)(bx * 128 + lrow) * K + lk4;

    float acc[8][8];
#pragma unroll
    for (int i = 0; i < 8; ++i)
#pragma unroll
        for (int j = 0; j < 8; ++j) acc[i][j] = 0.0f;

    for (int k0 = 0; k0 < K; k0 += 8) {
        float4 av = *(const float4*)(Aptr + k0);
        float4 wv = *(const float4*)(Wptr + k0);
        As[lk4 + 0][lrow] = av.x; As[lk4 + 1][lrow] = av.y;
        As[lk4 + 2][lrow] = av.z; As[lk4 + 3][lrow] = av.w;
        Bs[lk4 + 0][lrow] = wv.x; Bs[lk4 + 1][lrow] = wv.y;
        Bs[lk4 + 2][lrow] = wv.z; Bs[lk4 + 3][lrow] = wv.w;
        __syncthreads();
#pragma unroll
        for (int k = 0; k < 8; ++k) {
            float ar[8], br[8];
            *(float4*)&ar[0] = *(const float4*)&As[k][ty * 4];
            *(float4*)&ar[4] = *(const float4*)&As[k][64 + ty * 4];
            *(float4*)&br[0] = *(const float4*)&Bs[k][tx * 4];
            *(float4*)&br[4] = *(const float4*)&Bs[k][64 + tx * 4];
#pragma unroll
            for (int i = 0; i < 8; ++i)
#pragma unroll
                for (int j = 0; j < 8; ++j)
                    acc[i][j] += ar[i] * br[j];
        }
        __syncthreads();
    }

#pragma unroll
    for (int i = 0; i < 8; ++i) {
        int row = by * 128 + ((i < 4) ? (ty * 4 + i) : (64 + ty * 4 + (i - 4)));
        float* crow = C + (long)row * N + bx * 128;
#pragma unroll
        for (int half = 0; half < 2; ++half) {
            int colbase = half * 64 + tx * 4;
            float4 r;
            r.x = acc[i][half * 4 + 0]; r.y = acc[i][half * 4 + 1];
            r.z = acc[i][half * 4 + 2]; r.w = acc[i][half * 4 + 3];
            if (HASBIAS) {
                float4 bv = *(const float4*)(bias + bx * 128 + colbase);
                r.x += bv.x; r.y += bv.y; r.z += bv.z; r.w += bv.w;
            }
            if (ACC) {
                float4 ov = *(const float4*)(crow + colbase);
                r.x += ov.x; r.y += ov.y; r.z += ov.z; r.w += ov.w;
            }
            *(float4*)(crow + colbase) = r;
        }
    }
}

// ===========================================================================
// TENSOR-CORE SECTION -- single-pass tf32 (smooth paths only; measured error
// contribution ~3e-4 vs 1e-3 threshold from the R3/R4 decomposition).
// ===========================================================================
__device__ __forceinline__ unsigned f2tf(float x) {
    unsigned u;
    asm("cvt.rna.tf32.f32 %0, %1;" : "=r"(u) : "f"(x));
    return u;
}

__device__ __forceinline__ void mma8(float* c, const unsigned* a, const unsigned* b) {
    asm volatile(
        "mma.sync.aligned.m16n8k8.row.col.f32.tf32.tf32.f32 "
        "{%0,%1,%2,%3},{%4,%5,%6,%7},{%8,%9},{%0,%1,%2,%3};"
        : "+f"(c[0]), "+f"(c[1]), "+f"(c[2]), "+f"(c[3])
        : "r"(a[0]), "r"(a[1]), "r"(a[2]), "r"(a[3]), "r"(b[0]), "r"(b[1]));
}

template<bool HASBIAS>
__global__ __launch_bounds__(256)
void gemm_tf32_k(const float* __restrict__ A, const float* __restrict__ W,
                 const float* __restrict__ bias, float* __restrict__ C,
                 int M, int N, int K)
{
    constexpr int BM = 128, BN = 128, BK = 16;
    constexpr int MT = 4, NT = 4;
    __shared__ float As[BK][BM + 8];
    __shared__ float Bs[BK][BN + 8];

    const int tid  = threadIdx.x;
    const int warp = tid >> 5, lane = tid & 31;
    const int wm = warp & 1, wn = warp >> 1;
    const int mW = wm * 64, nW = wn * 32;
    const int g = lane >> 2, q = lane & 3;
    const int bx = blockIdx.x, by = blockIdx.y;

    const int lr = tid >> 1;
    const int lk = (tid & 1) * 8;
    const float* Ag = A + (long)(by * BM + lr) * K + lk;
    const float* Wg = W + (long)(bx * BN + lr) * K + lk;

    float acc[MT][NT][4];
#pragma unroll
    for (int i = 0; i < MT; ++i)
#pragma unroll
        for (int j = 0; j < NT; ++j)
#pragma unroll
            for (int r = 0; r < 4; ++r) acc[i][j][r] = 0.0f;

    for (int k0 = 0; k0 < K; k0 += BK) {
        float4 a0 = *(const float4*)(Ag + k0);
        float4 a1 = *(const float4*)(Ag + k0 + 4);
        As[lk + 0][lr] = a0.x; As[lk + 1][lr] = a0.y;
        As[lk + 2][lr] = a0.z; As[lk + 3][lr] = a0.w;
        As[lk + 4][lr] = a1.x; As[lk + 5][lr] = a1.y;
        As[lk + 6][lr] = a1.z; As[lk + 7][lr] = a1.w;
        float4 w0 = *(const float4*)(Wg + k0);
        float4 w1 = *(const float4*)(Wg + k0 + 4);
        Bs[lk + 0][lr] = w0.x; Bs[lk + 1][lr] = w0.y;
        Bs[lk + 2][lr] = w0.z; Bs[lk + 3][lr] = w0.w;
        Bs[lk + 4][lr] = w1.x; Bs[lk + 5][lr] = w1.y;
        Bs[lk + 6][lr] = w1.z; Bs[lk + 7][lr] = w1.w;
        __syncthreads();

#pragma unroll
        for (int ks = 0; ks < BK; ks += 8) {
            unsigned af[MT][4];
            unsigned bf[NT][2];
#pragma unroll
            for (int i = 0; i < MT; ++i) {
                int m = mW + i * 16 + g;
                af[i][0] = f2tf(As[ks + q][m]);
                af[i][1] = f2tf(As[ks + q][m + 8]);
                af[i][2] = f2tf(As[ks + 4 + q][m]);
                af[i][3] = f2tf(As[ks + 4 + q][m + 8]);
            }
#pragma unroll
            for (int j = 0; j < NT; ++j) {
                int n = nW + j * 8 + g;
                bf[j][0] = f2tf(Bs[ks + q][n]);
                bf[j][1] = f2tf(Bs[ks + 4 + q][n]);
            }
#pragma unroll
            for (int i = 0; i < MT; ++i)
#pragma unroll
                for (int j = 0; j < NT; ++j)
                    mma8(acc[i][j], af[i], bf[j]);
        }
        __syncthreads();
    }

#pragma unroll
    for (int i = 0; i < MT; ++i) {
        int r0 = by * BM + mW + i * 16 + g;
#pragma unroll
        for (int j = 0; j < NT; ++j) {
            int c0 = bx * BN + nW + j * 8 + q * 2;
            float2 lo; lo.x = acc[i][j][0]; lo.y = acc[i][j][1];
            float2 hi; hi.x = acc[i][j][2]; hi.y = acc[i][j][3];
            if (HASBIAS) {
                float2 bv = *(const float2*)(bias + c0);
                lo.x += bv.x; lo.y += bv.y; hi.x += bv.x; hi.y += bv.y;
            }
            *(float2*)(C + (long)r0 * N + c0)       = lo;
            *(float2*)(C + (long)(r0 + 8) * N + c0) = hi;
        }
    }
}

// ---------------------------------------------------------------------------
// (B,T,S,D) -> (B,S,T,D) permute
// ---------------------------------------------------------------------------
__global__ void transpose_k(const float* __restrict__ x, float* __restrict__ xp)
{
    long idx = (long)blockIdx.x * blockDim.x + threadIdx.x;
    int d = idx & (D_ - 1);
    long r = idx >> 9;
    int t = (int)(r & (T_ - 1));
    long r2 = r >> 4;
    int s = (int)(r2 & (S_ - 1));
    int b = (int)(r2 >> 9);
    xp[idx] = x[(((long)(b * T_ + t)) * S_ + s) * D_ + d];
}

// ---------------------------------------------------------------------------
// Attention core per (token, head)
// ---------------------------------------------------------------------------
__global__ __launch_bounds__(128)
void attn_core_k(const float* __restrict__ q, const float* __restrict__ k,
                 const float* __restrict__ v, float* __restrict__ av)
{
    __shared__ float qs[16][128], ks[16][128], vsm[16][128];
    __shared__ float sc[16][17];
    const int tid = threadIdx.x;
    const long token = blockIdx.x >> 2;
    const int h = blockIdx.x & 3;
    const long base = token * 16 * 512 + h * 128;

#pragma unroll
    for (int t = 0; t < 16; ++t) {
        qs[t][tid]  = q[base + (long)t * 512 + tid];
        ks[t][tid]  = k[base + (long)t * 512 + tid];
        vsm[t][tid] = v[base + (long)t * 512 + tid];
    }
    __syncthreads();

    for (int p = tid; p < 256; p += 128) {
        int t = p >> 4, u = p & 15;
        float acc = 0.0f;
#pragma unroll
        for (int d = 0; d < 128; ++d) acc += qs[t][d] * ks[u][d];
        sc[t][u] = acc / 11.3137084989847612f;   // / sqrt(128)
    }
    __syncthreads();

    if (tid < 16) {
        int t = tid;
        float mx = sc[t][0];
#pragma unroll
        for (int u = 1; u < 16; ++u) mx = fmaxf(mx, sc[t][u]);
        float e[16], sum = 0.0f;
#pragma unroll
        for (int u = 0; u < 16; ++u) { e[u] = expf(sc[t][u] - mx); sum += e[u]; }
#pragma unroll
        for (int u = 0; u < 16; ++u) sc[t][u] = e[u] / sum;
    }
    __syncthreads();

#pragma unroll
    for (int t = 0; t < 16; ++t) {
        float acc = 0.0f;
#pragma unroll
        for (int u = 0; u < 16; ++u) acc += sc[t][u] * vsm[u][tid];
        av[base + (long)t * 512 + tid] = acc;
    }
}

// ---------------------------------------------------------------------------
// h = x + permute(out_attn); hmean = mean_t(h)
// ---------------------------------------------------------------------------
__global__ void finalize_k(const float* __restrict__ xspk, const float* __restrict__ oat,
                           float* __restrict__ hout, float* __restrict__ hmean)
{
    int idx = blockIdx.x * blockDim.x + threadIdx.x;  // over NTOK*D_
    int d   = idx & (D_ - 1);
    int tok = idx >> 9;
    int b   = tok >> 9;
    int s   = tok & (S_ - 1);
    float sum = 0.0f;
#pragma unroll
    for (int t = 0; t < 16; ++t) {
        long hidx = (((long)(b * T_ + t)) * S_ + s) * D_ + d;
        float val = xspk[hidx] + oat[(((long)tok) * T_ + t) * D_ + d];
        hout[hidx] = val;
        sum += val;
    }
    hmean[(long)tok * D_ + d] = sum * (1.0f / 16.0f);
}

// ---------------------------------------------------------------------------
// host
// ---------------------------------------------------------------------------
extern "C" void kernel_launch(void* const* d_in, const int* in_sizes, int n_in,
                              void* d_out, int out_size)
{
    const int*   ids  = (const int*)d_in[0];
    const float* emb  = (const float*)d_in[1];
    const float* scal = (const float*)d_in[2];
    const float* Aall = (const float*)d_in[3];
    const float* Ball = (const float*)d_in[4];
    const float* Call = (const float*)d_in[5];
    const float* Dall = (const float*)d_in[6];
    const float* wq = (const float*)d_in[7];   const float* bq = (const float*)d_in[8];
    const float* wk = (const float*)d_in[9];   const float* bk = (const float*)d_in[10];
    const float* wv = (const float*)d_in[11];  const float* bv = (const float*)d_in[12];
    const float* wo = (const float*)d_in[13];  const float* bo = (const float*)d_in[14];
    const float* wout = (const float*)d_in[15];const float* bout = (const float*)d_in[16];
    float* out = (float*)d_out;

    float* arena = nullptr;
    cudaGetSymbolAddress((void**)&arena, g_arena);

    float* spk0   = arena + OFF_SPK0;
    float* spk1   = arena + OFF_SPK1;
    float* xp     = arena + OFF_XP;
    float* qb     = arena + OFF_Q;     // OU during SSM phase
    float* kb     = arena + OFF_K;
    float* vb     = arena + OFF_V;
    float* hstate = arena + OFF_HST;
    float* hmean  = arena + OFF_HM;
    int*   cnt    = (int*)(arena + OFF_CNT);   // 16*64 state counts
    int*   flags  = (int*)(arena + OFF_FLG);
    float* Hall   = arena + OFF_HALL;
    float* OU     = qb;

    // -------- encode --------
    cudaMemsetAsync(spk0, 0, SPK * sizeof(float));
    cudaMemsetAsync(flags, 0, 48 * sizeof(int));
    encode_k<<<(NTOK * D_) / 256, 256>>>(ids, emb, scal, spk0, flags);

    // -------- SSM layers --------
    for (int l = 0; l < 2; ++l) {
        const float* Al = Aall + (long)l * DS_ * DS_;
        const float* Bl = Ball + (long)l * DS_ * D_;
        const float* Cl = Call + (long)l * D_ * DS_;
        const float* Dl = Dall + (long)l * D_ * D_;
        float* xin  = l ? spk1 : spk0;
        float* xout = l ? spk0 : spk1;
        int* fin  = flags + (l ? 16 : 0);
        int* fout = flags + (l ? 32 : 16);

        // zero hstate, v_s, v_o (contiguous) and state counts
        cudaMemsetAsync(hstate, 0,
                        ((long)NTOK * DS_ * 2 + (long)NTOK * D_) * sizeof(float));
        cudaMemsetAsync(cnt, 0, CNT_INTS * sizeof(int));

        // state recurrence (thr_s replayed in-kernel from counts)
        for (int t = 0; t < T_; ++t)
            step_state_k<<<NTOK / 16, 256>>>(xin, t, Al, Bl, hstate,
                                             arena + OFF_VS, cnt, fin + t, Hall);

        // hoisted output-path GEMMs (bitwise == per-step launches)
        sgemm_k<false, false><<<dim3(4, NROWS / 128), 256>>>(
            Hall, Cl, nullptr, OU, NROWS, D_, DS_,
            (long)NROWS * DS_, (long)DS_, 0L, NROWS, nullptr);
        sgemm_k<true, false><<<dim3(4, NROWS / 128), 256>>>(
            xin, Dl, nullptr, OU, NROWS, D_, D_,
            (long)NROWS * D_, (long)D_, 0L, NROWS, nullptr);

        // fused output LIF over all 16 steps (writes zeros on inactive steps)
        out_fused_k<<<D_ / 4, 256>>>(OU, fin, xout, fout);
    }
    // after 2 layers: attention input = spk0 (B,T,S,D)

    // -------- attention (single-pass tf32) --------
    transpose_k<<<(int)(SPK / 256), 256>>>(spk0, xp);
    const int MA = NROWS;  // 32768
    gemm_tf32_k<true><<<dim3(D_ / 128, MA / 128), 256>>>(xp, wq, bq, qb, MA, D_, D_);
    gemm_tf32_k<true><<<dim3(D_ / 128, MA / 128), 256>>>(xp, wk, bk, kb, MA, D_, D_);
    gemm_tf32_k<true><<<dim3(D_ / 128, MA / 128), 256>>>(xp, wv, bv, vb, MA, D_, D_);
    attn_core_k<<<NTOK * 4, 128>>>(qb, kb, vb, spk1);           // av -> spk1
    gemm_tf32_k<true><<<dim3(D_ / 128, MA / 128), 256>>>(spk1, wo, bo, kb, MA, D_, D_);

    // -------- residual + mean + outputs --------
    float* hout = ((long)out_size >= LOGITS_SZ + H_SZ) ? (out + LOGITS_SZ) : xp;
    finalize_k<<<(NTOK * D_) / 256, 256>>>(spk0, kb, hout, hmean);

    // logits (single-pass tf32)
    gemm_tf32_k<true><<<dim3(V_ / 128, NTOK / 128), 256>>>(
        hmean, wout, bout, out, NTOK, V_, D_);
}

// round 11
// speedup vs baseline: 2.0208x; 1.3235x over previous
#include <cuda_runtime.h>
#include <cuda_bf16.h>
#include <math.h>

// ---------------------------------------------------------------------------
// Problem constants
// ---------------------------------------------------------------------------
#define B_    4
#define S_    512
#define T_    16
#define D_    512
#define DS_   64
#define V_    32000
#define NTOK  2048              // B_*S_
#define NROWS 32768             // B_*T_*S_
#define DECAY 0.60653065971263342f   // exp(-1/2)

static const long SPK       = (long)NROWS * D_;   // 16,777,216 floats
static const long LOGITS_SZ = (long)NTOK * V_;    // 65,536,000 floats
static const long H_SZ      = SPK;

// arena offsets (floats)
static const long OFF_SPK0 = 0;
static const long OFF_SPK1 = SPK;
static const long OFF_XP   = 2 * SPK;
static const long OFF_Q    = 3 * SPK;             // doubles as OU (32768x512)
static const long OFF_K    = 4 * SPK;
static const long OFF_V    = 5 * SPK;
static const long OFF_HST  = 6 * SPK;                       // 2048 x 64
static const long OFF_VS   = OFF_HST + (long)NTOK * DS_;    // 2048 x 64
static const long OFF_VO   = OFF_VS  + (long)NTOK * DS_;    // 2048 x 512
static const long OFF_HM   = OFF_VO  + (long)NTOK * D_;     // 2048 x 512
static const long OFF_CNT  = OFF_HM  + (long)NTOK * D_;     // ints: 16*64
static const long CNT_INTS = 16 * 64;
static const long OFF_FLG  = OFF_CNT + CNT_INTS;            // 48 ints
static const long OFF_HALL = OFF_FLG + 64;                  // 32768 x 64
static const long ARENA_TOTAL = OFF_HALL + (long)NROWS * DS_;

__device__ __align__(256) float g_arena[ARENA_TOTAL];

// ===========================================================================
// SSM SECTION -- LIF arithmetic is BITWISE-IDENTICAL to R9 (passing): every
// (token,channel) chain accumulates in the same ascending n-then-d order with
// the same FFMA contraction; only the operand staging (smem transposes,
// tiling) changed.
// ===========================================================================

__global__ void encode_k(const int* __restrict__ ids, const float* __restrict__ emb,
                         const float* __restrict__ scaling,
                         float* __restrict__ spk, int* __restrict__ flag)
{
    int idx = blockIdx.x * blockDim.x + threadIdx.x;   // over NTOK*D_
    int d   = idx & (D_ - 1);
    int tok = idx >> 9;
    int b   = tok >> 9;
    int s   = tok & (S_ - 1);
    float e = emb[(long)ids[tok] * D_ + d];
    float a = 1.0f / (1.0f + expf(-(*scaling) * e));
    float tr = rintf(10.0f * (1.0f - a));
    int ti = (int)tr;
    if (ti < 0) ti = 0;
    if (ti > T_ - 1) ti = T_ - 1;
    spk[(((long)(b * T_ + ti)) * S_ + s) * D_ + d] = 1.0f;
    flag[ti] = 1;
}

// State step with in-kernel thr_s replay and smem-staged transposed operands.
__global__ __launch_bounds__(256)
void step_state_k(const float* __restrict__ spk_in, int t,
                  const float* __restrict__ Amat, const float* __restrict__ Bmat,
                  float* __restrict__ hstate, float* __restrict__ vs,
                  int* __restrict__ cnt, const int* __restrict__ flag,
                  float* __restrict__ Hall)
{
    __shared__ float At[DS_][DS_ + 1];     // At[n][m]
    __shared__ float Bt[64][DS_ + 1];      // Bt[dl][m], per 64-wide d-tile
    __shared__ float xs[16][64];           // x tile [token][dl]
    __shared__ float hs[16][68];           // h [token][n], 272B rows (f4-ok)

    const int tid  = threadIdx.x;
    const int m    = tid & 63;
    const int lt   = tid >> 6;          // 0..3
    const int tok0 = blockIdx.x * 16;
    const int active = flag[0];

    // stage A transposed (coalesced read, conflict-free write)
    for (int i = tid; i < DS_ * DS_; i += 256) {
        int r = i >> 6, n = i & 63;     // read Amat[r*64+n] coalesced
        At[n][r] = Amat[i];
    }
    for (int i = tid; i < 16 * DS_; i += 256) {
        int tk = i >> 6, c = i & 63;
        hs[tk][c] = hstate[(long)(tok0 + tk) * DS_ + c];
    }
    // thr_s replay: identical float op sequence to the iterative updates
    float thr = 1.0f;
    for (int tp = 0; tp < t; ++tp) {
        float mean = (float)cnt[tp * 64 + m] * (1.0f / 2048.0f);
        thr += 0.1f * (mean - 0.1f);
    }
    __syncthreads();

    float acc[4];
#pragma unroll
    for (int j = 0; j < 4; ++j) acc[j] = 0.0f;

    // h @ A^T : ascending n, one chain per (token, m) -- same order as R9
    for (int n = 0; n < DS_; n += 4) {
        float a0 = At[n + 0][m];
        float a1 = At[n + 1][m];
        float a2 = At[n + 2][m];
        float a3 = At[n + 3][m];
#pragma unroll
        for (int j = 0; j < 4; ++j) {
            float4 hv = *(const float4*)&hs[lt + 4 * j][n];
            acc[j] += hv.x * a0;
            acc[j] += hv.y * a1;
            acc[j] += hv.z * a2;
            acc[j] += hv.w * a3;
        }
    }

    // x @ B^T : d tiled by 64, ascending d overall -- same order as R9
    if (active) {
        for (int dt = 0; dt < D_ / 64; ++dt) {
            __syncthreads();   // previous tile fully consumed
            for (int i = tid; i < DS_ * 64; i += 256) {
                int r = i >> 6, dl = i & 63;   // read Bmat row r coalesced
                Bt[dl][r] = Bmat[(long)r * D_ + dt * 64 + dl];
            }
            for (int i = tid; i < 16 * 64; i += 256) {
                int tk = i >> 6, dl = i & 63;
                int tok = tok0 + tk;
                int b = tok >> 9, s = tok & (S_ - 1);
                xs[tk][dl] = spk_in[(((long)(b * T_ + t)) * S_ + s) * D_
                                    + dt * 64 + dl];
            }
            __syncthreads();
            for (int dl = 0; dl < 64; dl += 4) {
                float b0 = Bt[dl + 0][m];
                float b1 = Bt[dl + 1][m];
                float b2 = Bt[dl + 2][m];
                float b3 = Bt[dl + 3][m];
#pragma unroll
                for (int j = 0; j < 4; ++j) {
                    float4 xv = *(const float4*)&xs[lt + 4 * j][dl];
                    acc[j] += xv.x * b0;
                    acc[j] += xv.y * b1;
                    acc[j] += xv.z * b2;
                    acc[j] += xv.w * b3;
                }
            }
        }
    }

    int c = 0;
#pragma unroll
    for (int j = 0; j < 4; ++j) {
        int tk = lt + 4 * j;
        int tok = tok0 + tk;
        long idx = (long)tok * DS_ + m;
        float v = vs[idx] * DECAY + acc[j];
        float sp = (v - thr >= 0.0f) ? 1.0f : 0.0f;
        v *= (1.0f - sp);
        vs[idx] = v;
        hstate[idx] = sp;
        int b = tok >> 9, s = tok & (S_ - 1);
        Hall[(((long)(b * T_ + t)) * S_ + s) * DS_ + m] = sp;
        c += (int)sp;
    }
    if (c) atomicAdd(&cnt[t * 64 + m], c);
}

// Fused output LIF over all 16 steps (unchanged from R9 -- passing).
__global__ __launch_bounds__(256)
void out_fused_k(const float* __restrict__ OU, const int* __restrict__ flags,
                 float* __restrict__ spk_out, int* __restrict__ flags_next)
{
    const int tid = threadIdx.x;
    const int el  = tid & 3;
    const int e   = blockIdx.x * 4 + el;
    const int ts  = tid >> 2;                 // 0..63
    __shared__ int scnt[4];

    float v[32];
#pragma unroll
    for (int j = 0; j < 32; ++j) v[j] = 0.0f;
    float thr = 1.0f;

    for (int t = 0; t < T_; ++t) {
        int act = flags[t];
        if (tid < 4) scnt[tid] = 0;
        __syncthreads();
        if (act) {
            int c = 0;
#pragma unroll
            for (int j = 0; j < 32; ++j) {
                int tok = ts + 64 * j;
                int b = tok >> 9, s = tok & (S_ - 1);
                long row = (long)b * (T_ * S_) + (long)t * S_ + s;
                float vv = v[j] * DECAY + OU[row * D_ + e];
                float sp = (vv - thr >= 0.0f) ? 1.0f : 0.0f;
                v[j] = vv * (1.0f - sp);
                spk_out[row * D_ + e] = sp;
                c += (int)sp;
            }
            if (c) atomicAdd(&scnt[el], c);
        } else {
#pragma unroll
            for (int j = 0; j < 32; ++j) {
                int tok = ts + 64 * j;
                int b = tok >> 9, s = tok & (S_ - 1);
                long row = (long)b * (T_ * S_) + (long)t * S_ + s;
                spk_out[row * D_ + e] = 0.0f;
            }
        }
        __syncthreads();
        if (act) {
            int cc = scnt[el];
            float mean = (float)cc * (1.0f / 2048.0f);
            thr += 0.1f * (mean - 0.1f);
            if (tid == 0 && (scnt[0] | scnt[1] | scnt[2] | scnt[3]))
                flags_next[t] = 1;
        }
        __syncthreads();
    }
}

// fp32 SGEMM -- verbatim round-2 kernel (k-sequential chain per output row).
template<bool ACC, bool HASBIAS>
__global__ __launch_bounds__(256)
void sgemm_k(const float* __restrict__ A, const float* __restrict__ W,
             const float* __restrict__ bias, float* __restrict__ C,
             int M, int N, int K,
             long aOuter, long aInner, long aConst, int aSdiv,
             const int* __restrict__ flag)
{
    if (flag && flag[0] == 0) return;
    __shared__ float As[8][128];
    __shared__ float Bs[8][128];
    const int tid = threadIdx.x;
    const int bx = blockIdx.x, by = blockIdx.y;
    const int tx = tid & 15, ty = tid >> 4;

    const int lrow = tid >> 1;
    const int lk4  = (tid & 1) * 4;

    const int arow = by * 128 + lrow;
    const long aoff = (long)(arow / aSdiv) * aOuter + (long)(arow % aSdiv) * aInner + aConst;
    const float* Aptr = A + aoff + lk4;
    const float* Wptr = W + (long)(bx * 128 + lrow) * K + lk4;

    float acc[8][8];
#pragma unroll
    for (int i = 0; i < 8; ++i)
#pragma unroll
        for (int j = 0; j < 8; ++j) acc[i][j] = 0.0f;

    for (int k0 = 0; k0 < K; k0 += 8) {
        float4 av = *(const float4*)(Aptr + k0);
        float4 wv = *(const float4*)(Wptr + k0);
        As[lk4 + 0][lrow] = av.x; As[lk4 + 1][lrow] = av.y;
        As[lk4 + 2][lrow] = av.z; As[lk4 + 3][lrow] = av.w;
        Bs[lk4 + 0][lrow] = wv.x; Bs[lk4 + 1][lrow] = wv.y;
        Bs[lk4 + 2][lrow] = wv.z; Bs[lk4 + 3][lrow] = wv.w;
        __syncthreads();
#pragma unroll
        for (int k = 0; k < 8; ++k) {
            float ar[8], br[8];
            *(float4*)&ar[0] = *(const float4*)&As[k][ty * 4];
            *(float4*)&ar[4] = *(const float4*)&As[k][64 + ty * 4];
            *(float4*)&br[0] = *(const float4*)&Bs[k][tx * 4];
            *(float4*)&br[4] = *(const float4*)&Bs[k][64 + tx * 4];
#pragma unroll
            for (int i = 0; i < 8; ++i)
#pragma unroll
                for (int j = 0; j < 8; ++j)
                    acc[i][j] += ar[i] * br[j];
        }
        __syncthreads();
    }

#pragma unroll
    for (int i = 0; i < 8; ++i) {
        int row = by * 128 + ((i < 4) ? (ty * 4 + i) : (64 + ty * 4 + (i - 4)));
        float* crow = C + (long)row * N + bx * 128;
#pragma unroll
        for (int half = 0; half < 2; ++half) {
            int colbase = half * 64 + tx * 4;
            float4 r;
            r.x = acc[i][half * 4 + 0]; r.y = acc[i][half * 4 + 1];
            r.z = acc[i][half * 4 + 2]; r.w = acc[i][half * 4 + 3];
            if (HASBIAS) {
                float4 bv = *(const float4*)(bias + bx * 128 + colbase);
                r.x += bv.x; r.y += bv.y; r.z += bv.z; r.w += bv.w;
            }
            if (ACC) {
                float4 ov = *(const float4*)(crow + colbase);
                r.x += ov.x; r.y += ov.y; r.z += ov.z; r.w += ov.w;
            }
            *(float4*)(crow + colbase) = r;
        }
    }
}

// ===========================================================================
// TENSOR-CORE SECTION -- single-pass tf32 (smooth paths only).
// ===========================================================================
__device__ __forceinline__ unsigned f2tf(float x) {
    unsigned u;
    asm("cvt.rna.tf32.f32 %0, %1;" : "=r"(u) : "f"(x));
    return u;
}

__device__ __forceinline__ void mma8(float* c, const unsigned* a, const unsigned* b) {
    asm volatile(
        "mma.sync.aligned.m16n8k8.row.col.f32.tf32.tf32.f32 "
        "{%0,%1,%2,%3},{%4,%5,%6,%7},{%8,%9},{%0,%1,%2,%3};"
        : "+f"(c[0]), "+f"(c[1]), "+f"(c[2]), "+f"(c[3])
        : "r"(a[0]), "r"(a[1]), "r"(a[2]), "r"(a[3]), "r"(b[0]), "r"(b[1]));
}

template<bool HASBIAS>
__global__ __launch_bounds__(256)
void gemm_tf32_k(const float* __restrict__ A, const float* __restrict__ W,
                 const float* __restrict__ bias, float* __restrict__ C,
                 int M, int N, int K)
{
    constexpr int BM = 128, BN = 128, BK = 16;
    constexpr int MT = 4, NT = 4;
    __shared__ float As[BK][BM + 8];
    __shared__ float Bs[BK][BN + 8];

    const int tid  = threadIdx.x;
    const int warp = tid >> 5, lane = tid & 31;
    const int wm = warp & 1, wn = warp >> 1;
    const int mW = wm * 64, nW = wn * 32;
    const int g = lane >> 2, q = lane & 3;
    const int bx = blockIdx.x, by = blockIdx.y;

    const int lr = tid >> 1;
    const int lk = (tid & 1) * 8;
    const float* Ag = A + (long)(by * BM + lr) * K + lk;
    const float* Wg = W + (long)(bx * BN + lr) * K + lk;

    float acc[MT][NT][4];
#pragma unroll
    for (int i = 0; i < MT; ++i)
#pragma unroll
        for (int j = 0; j < NT; ++j)
#pragma unroll
            for (int r = 0; r < 4; ++r) acc[i][j][r] = 0.0f;

    for (int k0 = 0; k0 < K; k0 += BK) {
        float4 a0 = *(const float4*)(Ag + k0);
        float4 a1 = *(const float4*)(Ag + k0 + 4);
        As[lk + 0][lr] = a0.x; As[lk + 1][lr] = a0.y;
        As[lk + 2][lr] = a0.z; As[lk + 3][lr] = a0.w;
        As[lk + 4][lr] = a1.x; As[lk + 5][lr] = a1.y;
        As[lk + 6][lr] = a1.z; As[lk + 7][lr] = a1.w;
        float4 w0 = *(const float4*)(Wg + k0);
        float4 w1 = *(const float4*)(Wg + k0 + 4);
        Bs[lk + 0][lr] = w0.x; Bs[lk + 1][lr] = w0.y;
        Bs[lk + 2][lr] = w0.z; Bs[lk + 3][lr] = w0.w;
        Bs[lk + 4][lr] = w1.x; Bs[lk + 5][lr] = w1.y;
        Bs[lk + 6][lr] = w1.z; Bs[lk + 7][lr] = w1.w;
        __syncthreads();

#pragma unroll
        for (int ks = 0; ks < BK; ks += 8) {
            unsigned af[MT][4];
            unsigned bf[NT][2];
#pragma unroll
            for (int i = 0; i < MT; ++i) {
                int m = mW + i * 16 + g;
                af[i][0] = f2tf(As[ks + q][m]);
                af[i][1] = f2tf(As[ks + q][m + 8]);
                af[i][2] = f2tf(As[ks + 4 + q][m]);
                af[i][3] = f2tf(As[ks + 4 + q][m + 8]);
            }
#pragma unroll
            for (int j = 0; j < NT; ++j) {
                int n = nW + j * 8 + g;
                bf[j][0] = f2tf(Bs[ks + q][n]);
                bf[j][1] = f2tf(Bs[ks + 4 + q][n]);
            }
#pragma unroll
            for (int i = 0; i < MT; ++i)
#pragma unroll
                for (int j = 0; j < NT; ++j)
                    mma8(acc[i][j], af[i], bf[j]);
        }
        __syncthreads();
    }

#pragma unroll
    for (int i = 0; i < MT; ++i) {
        int r0 = by * BM + mW + i * 16 + g;
#pragma unroll
        for (int j = 0; j < NT; ++j) {
            int c0 = bx * BN + nW + j * 8 + q * 2;
            float2 lo; lo.x = acc[i][j][0]; lo.y = acc[i][j][1];
            float2 hi; hi.x = acc[i][j][2]; hi.y = acc[i][j][3];
            if (HASBIAS) {
                float2 bv = *(const float2*)(bias + c0);
                lo.x += bv.x; lo.y += bv.y; hi.x += bv.x; hi.y += bv.y;
            }
            *(float2*)(C + (long)r0 * N + c0)       = lo;
            *(float2*)(C + (long)(r0 + 8) * N + c0) = hi;
        }
    }
}

// ---------------------------------------------------------------------------
// (B,T,S,D) -> (B,S,T,D) permute
// ---------------------------------------------------------------------------
__global__ void transpose_k(const float* __restrict__ x, float* __restrict__ xp)
{
    long idx = (long)blockIdx.x * blockDim.x + threadIdx.x;
    int d = idx & (D_ - 1);
    long r = idx >> 9;
    int t = (int)(r & (T_ - 1));
    long r2 = r >> 4;
    int s = (int)(r2 & (S_ - 1));
    int b = (int)(r2 >> 9);
    xp[idx] = x[(((long)(b * T_ + t)) * S_ + s) * D_ + d];
}

// ---------------------------------------------------------------------------
// Attention core per (token, head)
// ---------------------------------------------------------------------------
__global__ __launch_bounds__(128)
void attn_core_k(const float* __restrict__ q, const float* __restrict__ k,
                 const float* __restrict__ v, float* __restrict__ av)
{
    __shared__ float qs[16][128], ks[16][128], vsm[16][128];
    __shared__ float sc[16][17];
    const int tid = threadIdx.x;
    const long token = blockIdx.x >> 2;
    const int h = blockIdx.x & 3;
    const long base = token * 16 * 512 + h * 128;

#pragma unroll
    for (int t = 0; t < 16; ++t) {
        qs[t][tid]  = q[base + (long)t * 512 + tid];
        ks[t][tid]  = k[base + (long)t * 512 + tid];
        vsm[t][tid] = v[base + (long)t * 512 + tid];
    }
    __syncthreads();

    for (int p = tid; p < 256; p += 128) {
        int t = p >> 4, u = p & 15;
        float acc = 0.0f;
#pragma unroll
        for (int d = 0; d < 128; ++d) acc += qs[t][d] * ks[u][d];
        sc[t][u] = acc / 11.3137084989847612f;   // / sqrt(128)
    }
    __syncthreads();

    if (tid < 16) {
        int t = tid;
        float mx = sc[t][0];
#pragma unroll
        for (int u = 1; u < 16; ++u) mx = fmaxf(mx, sc[t][u]);
        float e[16], sum = 0.0f;
#pragma unroll
        for (int u = 0; u < 16; ++u) { e[u] = expf(sc[t][u] - mx); sum += e[u]; }
#pragma unroll
        for (int u = 0; u < 16; ++u) sc[t][u] = e[u] / sum;
    }
    __syncthreads();

#pragma unroll
    for (int t = 0; t < 16; ++t) {
        float acc = 0.0f;
#pragma unroll
        for (int u = 0; u < 16; ++u) acc += sc[t][u] * vsm[u][tid];
        av[base + (long)t * 512 + tid] = acc;
    }
}

// ---------------------------------------------------------------------------
// h = x + permute(out_attn); hmean = mean_t(h)
// ---------------------------------------------------------------------------
__global__ void finalize_k(const float* __restrict__ xspk, const float* __restrict__ oat,
                           float* __restrict__ hout, float* __restrict__ hmean)
{
    int idx = blockIdx.x * blockDim.x + threadIdx.x;  // over NTOK*D_
    int d   = idx & (D_ - 1);
    int tok = idx >> 9;
    int b   = tok >> 9;
    int s   = tok & (S_ - 1);
    float sum = 0.0f;
#pragma unroll
    for (int t = 0; t < 16; ++t) {
        long hidx = (((long)(b * T_ + t)) * S_ + s) * D_ + d;
        float val = xspk[hidx] + oat[(((long)tok) * T_ + t) * D_ + d];
        hout[hidx] = val;
        sum += val;
    }
    hmean[(long)tok * D_ + d] = sum * (1.0f / 16.0f);
}

// ---------------------------------------------------------------------------
// host
// ---------------------------------------------------------------------------
extern "C" void kernel_launch(void* const* d_in, const int* in_sizes, int n_in,
                              void* d_out, int out_size)
{
    const int*   ids  = (const int*)d_in[0];
    const float* emb  = (const float*)d_in[1];
    const float* scal = (const float*)d_in[2];
    const float* Aall = (const float*)d_in[3];
    const float* Ball = (const float*)d_in[4];
    const float* Call = (const float*)d_in[5];
    const float* Dall = (const float*)d_in[6];
    const float* wq = (const float*)d_in[7];   const float* bq = (const float*)d_in[8];
    const float* wk = (const float*)d_in[9];   const float* bk = (const float*)d_in[10];
    const float* wv = (const float*)d_in[11];  const float* bv = (const float*)d_in[12];
    const float* wo = (const float*)d_in[13];  const float* bo = (const float*)d_in[14];
    const float* wout = (const float*)d_in[15];const float* bout = (const float*)d_in[16];
    float* out = (float*)d_out;

    float* arena = nullptr;
    cudaGetSymbolAddress((void**)&arena, g_arena);

    float* spk0   = arena + OFF_SPK0;
    float* spk1   = arena + OFF_SPK1;
    float* xp     = arena + OFF_XP;
    float* qb     = arena + OFF_Q;     // OU during SSM phase
    float* kb     = arena + OFF_K;
    float* vb     = arena + OFF_V;
    float* hstate = arena + OFF_HST;
    float* hmean  = arena + OFF_HM;
    int*   cnt    = (int*)(arena + OFF_CNT);   // 16*64 state counts
    int*   flags  = (int*)(arena + OFF_FLG);
    float* Hall   = arena + OFF_HALL;
    float* OU     = qb;

    // -------- encode --------
    cudaMemsetAsync(spk0, 0, SPK * sizeof(float));
    cudaMemsetAsync(flags, 0, 48 * sizeof(int));
    encode_k<<<(NTOK * D_) / 256, 256>>>(ids, emb, scal, spk0, flags);

    // -------- SSM layers --------
    for (int l = 0; l < 2; ++l) {
        const float* Al = Aall + (long)l * DS_ * DS_;
        const float* Bl = Ball + (long)l * DS_ * D_;
        const float* Cl = Call + (long)l * D_ * DS_;
        const float* Dl = Dall + (long)l * D_ * D_;
        float* xin  = l ? spk1 : spk0;
        float* xout = l ? spk0 : spk1;
        int* fin  = flags + (l ? 16 : 0);
        int* fout = flags + (l ? 32 : 16);

        // zero hstate, v_s, v_o (contiguous) and state counts
        cudaMemsetAsync(hstate, 0,
                        ((long)NTOK * DS_ * 2 + (long)NTOK * D_) * sizeof(float));
        cudaMemsetAsync(cnt, 0, CNT_INTS * sizeof(int));

        // state recurrence (thr_s replayed in-kernel from counts)
        for (int t = 0; t < T_; ++t)
            step_state_k<<<NTOK / 16, 256>>>(xin, t, Al, Bl, hstate,
                                             arena + OFF_VS, cnt, fin + t, Hall);

        // hoisted output-path GEMMs (bitwise == per-step launches)
        sgemm_k<false, false><<<dim3(4, NROWS / 128), 256>>>(
            Hall, Cl, nullptr, OU, NROWS, D_, DS_,
            (long)NROWS * DS_, (long)DS_, 0L, NROWS, nullptr);
        sgemm_k<true, false><<<dim3(4, NROWS / 128), 256>>>(
            xin, Dl, nullptr, OU, NROWS, D_, D_,
            (long)NROWS * D_, (long)D_, 0L, NROWS, nullptr);

        // fused output LIF over all 16 steps (writes zeros on inactive steps)
        out_fused_k<<<D_ / 4, 256>>>(OU, fin, xout, fout);
    }
    // after 2 layers: attention input = spk0 (B,T,S,D)

    // -------- attention (single-pass tf32) --------
    transpose_k<<<(int)(SPK / 256), 256>>>(spk0, xp);
    const int MA = NROWS;  // 32768
    gemm_tf32_k<true><<<dim3(D_ / 128, MA / 128), 256>>>(xp, wq, bq, qb, MA, D_, D_);
    gemm_tf32_k<true><<<dim3(D_ / 128, MA / 128), 256>>>(xp, wk, bk, kb, MA, D_, D_);
    gemm_tf32_k<true><<<dim3(D_ / 128, MA / 128), 256>>>(xp, wv, bv, vb, MA, D_, D_);
    attn_core_k<<<NTOK * 4, 128>>>(qb, kb, vb, spk1);           // av -> spk1
    gemm_tf32_k<true><<<dim3(D_ / 128, MA / 128), 256>>>(spk1, wo, bo, kb, MA, D_, D_);

    // -------- residual + mean + outputs --------
    float* hout = ((long)out_size >= LOGITS_SZ + H_SZ) ? (out + LOGITS_SZ) : xp;
    finalize_k<<<(NTOK * D_) / 256, 256>>>(spk0, kb, hout, hmean);

    // logits (single-pass tf32)
    gemm_tf32_k<true><<<dim3(V_ / 128, NTOK / 128), 256>>>(
        hmean, wout, bout, out, NTOK, V_, D_);
}

// round 12
// speedup vs baseline: 2.3323x; 1.1541x over previous
#include <cuda_runtime.h>
#include <cuda_bf16.h>
#include <math.h>

// ---------------------------------------------------------------------------
// Problem constants
// ---------------------------------------------------------------------------
#define B_    4
#define S_    512
#define T_    16
#define D_    512
#define DS_   64
#define V_    32000
#define NTOK  2048              // B_*S_
#define NROWS 32768             // B_*T_*S_
#define DECAY 0.60653065971263342f   // exp(-1/2)
#define NBLK  128               // persistent state kernel grid

static const long SPK       = (long)NROWS * D_;   // 16,777,216 floats
static const long LOGITS_SZ = (long)NTOK * V_;    // 65,536,000 floats
static const long H_SZ      = SPK;

// arena offsets (floats)
static const long OFF_SPK0 = 0;
static const long OFF_SPK1 = SPK;
static const long OFF_XP   = 2 * SPK;
static const long OFF_Q    = 3 * SPK;             // doubles as OU (32768x512)
static const long OFF_K    = 4 * SPK;
static const long OFF_V    = 5 * SPK;
static const long OFF_HM   = 6 * SPK;                       // 2048 x 512
static const long OFF_CNT  = OFF_HM + (long)NTOK * D_;      // ints: 16*64
static const long CNT_INTS = 16 * 64;
static const long OFF_BAR  = OFF_CNT + CNT_INTS;            // 16 ints
static const long OFF_FLG  = OFF_BAR + 16;                  // 48 ints
static const long OFF_HALL = OFF_FLG + 64;                  // 32768 x 64
static const long ARENA_TOTAL = OFF_HALL + (long)NROWS * DS_;

__device__ __align__(256) float g_arena[ARENA_TOTAL];

// persistent state kernel smem layout (floats)
#define SM_AT    0                    // At[n][m] : 64 x 65
#define SM_BT    (64 * 65)            // Bt[d][m] : 512 x 65
#define SM_XS    (SM_BT + 512 * 65)   // xs[tk][d]: 16 x 512
#define SM_HS    (SM_XS + 16 * 512)   // hs[tk][m]: 16 x 68
#define SM_INT   (SM_HS + 16 * 68)    // scnt[64] + sflag[16]
#define SM_TOTAL (SM_INT + 80)
static const int SMEM_STATE_BYTES = SM_TOTAL * 4;   // 187,520 B

// ===========================================================================
// SSM SECTION -- LIF arithmetic is BITWISE-IDENTICAL to R11 (passing): every
// (token,channel) chain accumulates in the same ascending n-then-d order with
// the same FFMA expressions; h/v/thr now carried in smem/registers across the
// 16 steps inside ONE persistent launch per layer (grid barrier per step
// protects only the integer spike counts).
// ===========================================================================

__global__ void encode_k(const int* __restrict__ ids, const float* __restrict__ emb,
                         const float* __restrict__ scaling,
                         float* __restrict__ spk, int* __restrict__ flag)
{
    int idx = blockIdx.x * blockDim.x + threadIdx.x;   // over NTOK*D_
    int d   = idx & (D_ - 1);
    int tok = idx >> 9;
    int b   = tok >> 9;
    int s   = tok & (S_ - 1);
    float e = emb[(long)ids[tok] * D_ + d];
    float a = 1.0f / (1.0f + expf(-(*scaling) * e));
    float tr = rintf(10.0f * (1.0f - a));
    int ti = (int)tr;
    if (ti < 0) ti = 0;
    if (ti > T_ - 1) ti = T_ - 1;
    spk[(((long)(b * T_ + ti)) * S_ + s) * D_ + d] = 1.0f;
    flag[ti] = 1;
}

// Persistent per-layer state recurrence: 128 blocks x 256 threads, 1/SM.
__global__ __launch_bounds__(256)
void state_layer_k(const float* __restrict__ spk_in,
                   const float* __restrict__ Amat, const float* __restrict__ Bmat,
                   int* __restrict__ cnt, const int* __restrict__ flags,
                   float* __restrict__ Hall, int* __restrict__ bar)
{
    extern __shared__ float sm[];
    float* At = sm + SM_AT;
    float* Bt = sm + SM_BT;
    float* xs = sm + SM_XS;
    float* hs = sm + SM_HS;
    int*   scnt  = (int*)(sm + SM_INT);
    int*   sflag = scnt + 64;

    const int tid  = threadIdx.x;
    const int m    = tid & 63;
    const int lt   = tid >> 6;          // 0..3
    const int tok0 = blockIdx.x * 16;

    // stage A^T, B^T once (coalesced reads, conflict-free writes)
    for (int i = tid; i < DS_ * DS_; i += 256) {
        int r = i >> 6, n = i & 63;
        At[n * 65 + r] = Amat[i];
    }
    for (int i = tid; i < DS_ * D_; i += 256) {
        int mm = i >> 9, d = i & (D_ - 1);
        Bt[d * 65 + mm] = Bmat[i];
    }
    for (int i = tid; i < 16 * 68; i += 256) hs[i] = 0.0f;
    if (tid < 16) sflag[tid] = flags[tid];
    __syncthreads();

    float v[4];
#pragma unroll
    for (int j = 0; j < 4; ++j) v[j] = 0.0f;
    float thr = 1.0f;

    for (int t = 0; t < T_; ++t) {
        const int active = sflag[t];
        if (tid < 64) scnt[tid] = 0;
        if (active) {
            for (int i = tid; i < 16 * D_; i += 256) {
                int tk = i >> 9, d = i & (D_ - 1);
                int tok = tok0 + tk;
                int b = tok >> 9, s = tok & (S_ - 1);
                xs[tk * D_ + d] = spk_in[(((long)(b * T_ + t)) * S_ + s) * D_ + d];
            }
        }
        __syncthreads();   // xs staged, hs stable, scnt zeroed

        float acc[4];
#pragma unroll
        for (int j = 0; j < 4; ++j) acc[j] = 0.0f;

        // h @ A^T : ascending n -- identical expressions to R11
        for (int n = 0; n < DS_; n += 4) {
            float a0 = At[(n + 0) * 65 + m];
            float a1 = At[(n + 1) * 65 + m];
            float a2 = At[(n + 2) * 65 + m];
            float a3 = At[(n + 3) * 65 + m];
#pragma unroll
            for (int j = 0; j < 4; ++j) {
                float4 hv = *(const float4*)&hs[(lt + 4 * j) * 68 + n];
                acc[j] += hv.x * a0;
                acc[j] += hv.y * a1;
                acc[j] += hv.z * a2;
                acc[j] += hv.w * a3;
            }
        }
        // x @ B^T : ascending d (full 512, no tiling) -- identical expressions
        if (active) {
            for (int d = 0; d < D_; d += 4) {
                float b0 = Bt[(d + 0) * 65 + m];
                float b1 = Bt[(d + 1) * 65 + m];
                float b2 = Bt[(d + 2) * 65 + m];
                float b3 = Bt[(d + 3) * 65 + m];
#pragma unroll
                for (int j = 0; j < 4; ++j) {
                    float4 xv = *(const float4*)&xs[(lt + 4 * j) * D_ + d];
                    acc[j] += xv.x * b0;
                    acc[j] += xv.y * b1;
                    acc[j] += xv.z * b2;
                    acc[j] += xv.w * b3;
                }
            }
        }
        __syncthreads();   // all hs reads complete before LIF writes

        int c = 0;
#pragma unroll
        for (int j = 0; j < 4; ++j) {
            int tk = lt + 4 * j;
            int tok = tok0 + tk;
            float vv = v[j] * DECAY + acc[j];
            float sp = (vv - thr >= 0.0f) ? 1.0f : 0.0f;
            v[j] = vv * (1.0f - sp);
            hs[tk * 68 + m] = sp;
            int b = tok >> 9, s = tok & (S_ - 1);
            Hall[(((long)(b * T_ + t)) * S_ + s) * DS_ + m] = sp;
            c += (int)sp;
        }
        if (c) atomicAdd(&scnt[m], c);
        __syncthreads();
        if (tid < 64 && scnt[tid]) atomicAdd(&cnt[t * 64 + tid], scnt[tid]);
        __threadfence();
        // grid barrier (monotonic counter; all NBLK blocks resident)
        if (tid == 0) {
            atomicAdd(bar, 1);
            while (*((volatile int*)bar) < NBLK * (t + 1)) { }
        }
        __syncthreads();
        // thr ladder: same float op sequence as the per-step replay
        {
            float mean = (float)(*((volatile int*)&cnt[t * 64 + m])) * (1.0f / 2048.0f);
            thr += 0.1f * (mean - 0.1f);
        }
        __syncthreads();
    }
}

// Fused output LIF over all 16 steps (unchanged from R9/R11 -- passing).
__global__ __launch_bounds__(256)
void out_fused_k(const float* __restrict__ OU, const int* __restrict__ flags,
                 float* __restrict__ spk_out, int* __restrict__ flags_next)
{
    const int tid = threadIdx.x;
    const int el  = tid & 3;
    const int e   = blockIdx.x * 4 + el;
    const int ts  = tid >> 2;                 // 0..63
    __shared__ int scnt[4];

    float v[32];
#pragma unroll
    for (int j = 0; j < 32; ++j) v[j] = 0.0f;
    float thr = 1.0f;

    for (int t = 0; t < T_; ++t) {
        int act = flags[t];
        if (tid < 4) scnt[tid] = 0;
        __syncthreads();
        if (act) {
            int c = 0;
#pragma unroll
            for (int j = 0; j < 32; ++j) {
                int tok = ts + 64 * j;
                int b = tok >> 9, s = tok & (S_ - 1);
                long row = (long)b * (T_ * S_) + (long)t * S_ + s;
                float vv = v[j] * DECAY + OU[row * D_ + e];
                float sp = (vv - thr >= 0.0f) ? 1.0f : 0.0f;
                v[j] = vv * (1.0f - sp);
                spk_out[row * D_ + e] = sp;
                c += (int)sp;
            }
            if (c) atomicAdd(&scnt[el], c);
        } else {
#pragma unroll
            for (int j = 0; j < 32; ++j) {
                int tok = ts + 64 * j;
                int b = tok >> 9, s = tok & (S_ - 1);
                long row = (long)b * (T_ * S_) + (long)t * S_ + s;
                spk_out[row * D_ + e] = 0.0f;
            }
        }
        __syncthreads();
        if (act) {
            int cc = scnt[el];
            float mean = (float)cc * (1.0f / 2048.0f);
            thr += 0.1f * (mean - 0.1f);
            if (tid == 0 && (scnt[0] | scnt[1] | scnt[2] | scnt[3]))
                flags_next[t] = 1;
        }
        __syncthreads();
    }
}

// fp32 SGEMM -- verbatim round-2 kernel (k-sequential chain per output row).
template<bool ACC, bool HASBIAS>
__global__ __launch_bounds__(256)
void sgemm_k(const float* __restrict__ A, const float* __restrict__ W,
             const float* __restrict__ bias, float* __restrict__ C,
             int M, int N, int K,
             long aOuter, long aInner, long aConst, int aSdiv,
             const int* __restrict__ flag)
{
    if (flag && flag[0] == 0) return;
    __shared__ float As[8][128];
    __shared__ float Bs[8][128];
    const int tid = threadIdx.x;
    const int bx = blockIdx.x, by = blockIdx.y;
    const int tx = tid & 15, ty = tid >> 4;

    const int lrow = tid >> 1;
    const int lk4  = (tid & 1) * 4;

    const int arow = by * 128 + lrow;
    const long aoff = (long)(arow / aSdiv) * aOuter + (long)(arow % aSdiv) * aInner + aConst;
    const float* Aptr = A + aoff + lk4;
    const float* Wptr = W + (long)(bx * 128 + lrow) * K + lk4;

    float acc[8][8];
#pragma unroll
    for (int i = 0; i < 8; ++i)
#pragma unroll
        for (int j = 0; j < 8; ++j) acc[i][j] = 0.0f;

    for (int k0 = 0; k0 < K; k0 += 8) {
        float4 av = *(const float4*)(Aptr + k0);
        float4 wv = *(const float4*)(Wptr + k0);
        As[lk4 + 0][lrow] = av.x; As[lk4 + 1][lrow] = av.y;
        As[lk4 + 2][lrow] = av.z; As[lk4 + 3][lrow] = av.w;
        Bs[lk4 + 0][lrow] = wv.x; Bs[lk4 + 1][lrow] = wv.y;
        Bs[lk4 + 2][lrow] = wv.z; Bs[lk4 + 3][lrow] = wv.w;
        __syncthreads();
#pragma unroll
        for (int k = 0; k < 8; ++k) {
            float ar[8], br[8];
            *(float4*)&ar[0] = *(const float4*)&As[k][ty * 4];
            *(float4*)&ar[4] = *(const float4*)&As[k][64 + ty * 4];
            *(float4*)&br[0] = *(const float4*)&Bs[k][tx * 4];
            *(float4*)&br[4] = *(const float4*)&Bs[k][64 + tx * 4];
#pragma unroll
            for (int i = 0; i < 8; ++i)
#pragma unroll
                for (int j = 0; j < 8; ++j)
                    acc[i][j] += ar[i] * br[j];
        }
        __syncthreads();
    }

#pragma unroll
    for (int i = 0; i < 8; ++i) {
        int row = by * 128 + ((i < 4) ? (ty * 4 + i) : (64 + ty * 4 + (i - 4)));
        float* crow = C + (long)row * N + bx * 128;
#pragma unroll
        for (int half = 0; half < 2; ++half) {
            int colbase = half * 64 + tx * 4;
            float4 r;
            r.x = acc[i][half * 4 + 0]; r.y = acc[i][half * 4 + 1];
            r.z = acc[i][half * 4 + 2]; r.w = acc[i][half * 4 + 3];
            if (HASBIAS) {
                float4 bv = *(const float4*)(bias + bx * 128 + colbase);
                r.x += bv.x; r.y += bv.y; r.z += bv.z; r.w += bv.w;
            }
            if (ACC) {
                float4 ov = *(const float4*)(crow + colbase);
                r.x += ov.x; r.y += ov.y; r.z += ov.z; r.w += ov.w;
            }
            *(float4*)(crow + colbase) = r;
        }
    }
}

// ===========================================================================
// TENSOR-CORE SECTION -- single-pass tf32 (smooth paths only).
// ===========================================================================
__device__ __forceinline__ unsigned f2tf(float x) {
    unsigned u;
    asm("cvt.rna.tf32.f32 %0, %1;" : "=r"(u) : "f"(x));
    return u;
}

__device__ __forceinline__ void mma8(float* c, const unsigned* a, const unsigned* b) {
    asm volatile(
        "mma.sync.aligned.m16n8k8.row.col.f32.tf32.tf32.f32 "
        "{%0,%1,%2,%3},{%4,%5,%6,%7},{%8,%9},{%0,%1,%2,%3};"
        : "+f"(c[0]), "+f"(c[1]), "+f"(c[2]), "+f"(c[3])
        : "r"(a[0]), "r"(a[1]), "r"(a[2]), "r"(a[3]), "r"(b[0]), "r"(b[1]));
}

template<bool HASBIAS>
__global__ __launch_bounds__(256)
void gemm_tf32_k(const float* __restrict__ A, const float* __restrict__ W,
                 const float* __restrict__ bias, float* __restrict__ C,
                 int M, int N, int K)
{
    constexpr int BM = 128, BN = 128, BK = 16;
    constexpr int MT = 4, NT = 4;
    __shared__ float As[BK][BM + 8];
    __shared__ float Bs[BK][BN + 8];

    const int tid  = threadIdx.x;
    const int warp = tid >> 5, lane = tid & 31;
    const int wm = warp & 1, wn = warp >> 1;
    const int mW = wm * 64, nW = wn * 32;
    const int g = lane >> 2, q = lane & 3;
    const int bx = blockIdx.x, by = blockIdx.y;

    const int lr = tid >> 1;
    const int lk = (tid & 1) * 8;
    const float* Ag = A + (long)(by * BM + lr) * K + lk;
    const float* Wg = W + (long)(bx * BN + lr) * K + lk;

    float acc[MT][NT][4];
#pragma unroll
    for (int i = 0; i < MT; ++i)
#pragma unroll
        for (int j = 0; j < NT; ++j)
#pragma unroll
            for (int r = 0; r < 4; ++r) acc[i][j][r] = 0.0f;

    for (int k0 = 0; k0 < K; k0 += BK) {
        float4 a0 = *(const float4*)(Ag + k0);
        float4 a1 = *(const float4*)(Ag + k0 + 4);
        As[lk + 0][lr] = a0.x; As[lk + 1][lr] = a0.y;
        As[lk + 2][lr] = a0.z; As[lk + 3][lr] = a0.w;
        As[lk + 4][lr] = a1.x; As[lk + 5][lr] = a1.y;
        As[lk + 6][lr] = a1.z; As[lk + 7][lr] = a1.w;
        float4 w0 = *(const float4*)(Wg + k0);
        float4 w1 = *(const float4*)(Wg + k0 + 4);
        Bs[lk + 0][lr] = w0.x; Bs[lk + 1][lr] = w0.y;
        Bs[lk + 2][lr] = w0.z; Bs[lk + 3][lr] = w0.w;
        Bs[lk + 4][lr] = w1.x; Bs[lk + 5][lr] = w1.y;
        Bs[lk + 6][lr] = w1.z; Bs[lk + 7][lr] = w1.w;
        __syncthreads();

#pragma unroll
        for (int ks = 0; ks < BK; ks += 8) {
            unsigned af[MT][4];
            unsigned bf[NT][2];
#pragma unroll
            for (int i = 0; i < MT; ++i) {
                int m = mW + i * 16 + g;
                af[i][0] = f2tf(As[ks + q][m]);
                af[i][1] = f2tf(As[ks + q][m + 8]);
                af[i][2] = f2tf(As[ks + 4 + q][m]);
                af[i][3] = f2tf(As[ks + 4 + q][m + 8]);
            }
#pragma unroll
            for (int j = 0; j < NT; ++j) {
                int n = nW + j * 8 + g;
                bf[j][0] = f2tf(Bs[ks + q][n]);
                bf[j][1] = f2tf(Bs[ks + 4 + q][n]);
            }
#pragma unroll
            for (int i = 0; i < MT; ++i)
#pragma unroll
                for (int j = 0; j < NT; ++j)
                    mma8(acc[i][j], af[i], bf[j]);
        }
        __syncthreads();
    }

#pragma unroll
    for (int i = 0; i < MT; ++i) {
        int r0 = by * BM + mW + i * 16 + g;
#pragma unroll
        for (int j = 0; j < NT; ++j) {
            int c0 = bx * BN + nW + j * 8 + q * 2;
            float2 lo; lo.x = acc[i][j][0]; lo.y = acc[i][j][1];
            float2 hi; hi.x = acc[i][j][2]; hi.y = acc[i][j][3];
            if (HASBIAS) {
                float2 bv = *(const float2*)(bias + c0);
                lo.x += bv.x; lo.y += bv.y; hi.x += bv.x; hi.y += bv.y;
            }
            *(float2*)(C + (long)r0 * N + c0)       = lo;
            *(float2*)(C + (long)(r0 + 8) * N + c0) = hi;
        }
    }
}

// ---------------------------------------------------------------------------
// (B,T,S,D) -> (B,S,T,D) permute
// ---------------------------------------------------------------------------
__global__ void transpose_k(const float* __restrict__ x, float* __restrict__ xp)
{
    long idx = (long)blockIdx.x * blockDim.x + threadIdx.x;
    int d = idx & (D_ - 1);
    long r = idx >> 9;
    int t = (int)(r & (T_ - 1));
    long r2 = r >> 4;
    int s = (int)(r2 & (S_ - 1));
    int b = (int)(r2 >> 9);
    xp[idx] = x[(((long)(b * T_ + t)) * S_ + s) * D_ + d];
}

// ---------------------------------------------------------------------------
// Attention core per (token, head)
// ---------------------------------------------------------------------------
__global__ __launch_bounds__(128)
void attn_core_k(const float* __restrict__ q, const float* __restrict__ k,
                 const float* __restrict__ v, float* __restrict__ av)
{
    __shared__ float qs[16][128], ks[16][128], vsm[16][128];
    __shared__ float sc[16][17];
    const int tid = threadIdx.x;
    const long token = blockIdx.x >> 2;
    const int h = blockIdx.x & 3;
    const long base = token * 16 * 512 + h * 128;

#pragma unroll
    for (int t = 0; t < 16; ++t) {
        qs[t][tid]  = q[base + (long)t * 512 + tid];
        ks[t][tid]  = k[base + (long)t * 512 + tid];
        vsm[t][tid] = v[base + (long)t * 512 + tid];
    }
    __syncthreads();

    for (int p = tid; p < 256; p += 128) {
        int t = p >> 4, u = p & 15;
        float acc = 0.0f;
#pragma unroll
        for (int d = 0; d < 128; ++d) acc += qs[t][d] * ks[u][d];
        sc[t][u] = acc / 11.3137084989847612f;   // / sqrt(128)
    }
    __syncthreads();

    if (tid < 16) {
        int t = tid;
        float mx = sc[t][0];
#pragma unroll
        for (int u = 1; u < 16; ++u) mx = fmaxf(mx, sc[t][u]);
        float e[16], sum = 0.0f;
#pragma unroll
        for (int u = 0; u < 16; ++u) { e[u] = expf(sc[t][u] - mx); sum += e[u]; }
#pragma unroll
        for (int u = 0; u < 16; ++u) sc[t][u] = e[u] / sum;
    }
    __syncthreads();

#pragma unroll
    for (int t = 0; t < 16; ++t) {
        float acc = 0.0f;
#pragma unroll
        for (int u = 0; u < 16; ++u) acc += sc[t][u] * vsm[u][tid];
        av[base + (long)t * 512 + tid] = acc;
    }
}

// ---------------------------------------------------------------------------
// h = x + permute(out_attn); hmean = mean_t(h)
// ---------------------------------------------------------------------------
__global__ void finalize_k(const float* __restrict__ xspk, const float* __restrict__ oat,
                           float* __restrict__ hout, float* __restrict__ hmean)
{
    int idx = blockIdx.x * blockDim.x + threadIdx.x;  // over NTOK*D_
    int d   = idx & (D_ - 1);
    int tok = idx >> 9;
    int b   = tok >> 9;
    int s   = tok & (S_ - 1);
    float sum = 0.0f;
#pragma unroll
    for (int t = 0; t < 16; ++t) {
        long hidx = (((long)(b * T_ + t)) * S_ + s) * D_ + d;
        float val = xspk[hidx] + oat[(((long)tok) * T_ + t) * D_ + d];
        hout[hidx] = val;
        sum += val;
    }
    hmean[(long)tok * D_ + d] = sum * (1.0f / 16.0f);
}

// ---------------------------------------------------------------------------
// host
// ---------------------------------------------------------------------------
extern "C" void kernel_launch(void* const* d_in, const int* in_sizes, int n_in,
                              void* d_out, int out_size)
{
    const int*   ids  = (const int*)d_in[0];
    const float* emb  = (const float*)d_in[1];
    const float* scal = (const float*)d_in[2];
    const float* Aall = (const float*)d_in[3];
    const float* Ball = (const float*)d_in[4];
    const float* Call = (const float*)d_in[5];
    const float* Dall = (const float*)d_in[6];
    const float* wq = (const float*)d_in[7];   const float* bq = (const float*)d_in[8];
    const float* wk = (const float*)d_in[9];   const float* bk = (const float*)d_in[10];
    const float* wv = (const float*)d_in[11];  const float* bv = (const float*)d_in[12];
    const float* wo = (const float*)d_in[13];  const float* bo = (const float*)d_in[14];
    const float* wout = (const float*)d_in[15];const float* bout = (const float*)d_in[16];
    float* out = (float*)d_out;

    float* arena = nullptr;
    cudaGetSymbolAddress((void**)&arena, g_arena);

    float* spk0   = arena + OFF_SPK0;
    float* spk1   = arena + OFF_SPK1;
    float* xp     = arena + OFF_XP;
    float* qb     = arena + OFF_Q;     // OU during SSM phase
    float* kb     = arena + OFF_K;
    float* vb     = arena + OFF_V;
    float* hmean  = arena + OFF_HM;
    int*   cnt    = (int*)(arena + OFF_CNT);   // 16*64 state counts
    int*   bar    = (int*)(arena + OFF_BAR);
    int*   flags  = (int*)(arena + OFF_FLG);
    float* Hall   = arena + OFF_HALL;
    float* OU     = qb;

    cudaFuncSetAttribute(state_layer_k,
                         cudaFuncAttributeMaxDynamicSharedMemorySize,
                         SMEM_STATE_BYTES);

    // -------- encode --------
    cudaMemsetAsync(spk0, 0, SPK * sizeof(float));
    cudaMemsetAsync(flags, 0, 48 * sizeof(int));
    encode_k<<<(NTOK * D_) / 256, 256>>>(ids, emb, scal, spk0, flags);

    // -------- SSM layers --------
    for (int l = 0; l < 2; ++l) {
        const float* Al = Aall + (long)l * DS_ * DS_;
        const float* Bl = Ball + (long)l * DS_ * D_;
        const float* Cl = Call + (long)l * D_ * DS_;
        const float* Dl = Dall + (long)l * D_ * D_;
        float* xin  = l ? spk1 : spk0;
        float* xout = l ? spk0 : spk1;
        int* fin  = flags + (l ? 16 : 0);
        int* fout = flags + (l ? 32 : 16);

        // zero state counts + grid barrier counter (adjacent)
        cudaMemsetAsync(cnt, 0, (CNT_INTS + 16) * sizeof(int));

        // persistent state recurrence: all 16 steps in one launch
        state_layer_k<<<NBLK, 256, SMEM_STATE_BYTES>>>(
            xin, Al, Bl, cnt, fin, Hall, bar);

        // hoisted output-path GEMMs (bitwise == per-step launches)
        sgemm_k<false, false><<<dim3(4, NROWS / 128), 256>>>(
            Hall, Cl, nullptr, OU, NROWS, D_, DS_,
            (long)NROWS * DS_, (long)DS_, 0L, NROWS, nullptr);
        sgemm_k<true, false><<<dim3(4, NROWS / 128), 256>>>(
            xin, Dl, nullptr, OU, NROWS, D_, D_,
            (long)NROWS * D_, (long)D_, 0L, NROWS, nullptr);

        // fused output LIF over all 16 steps (writes zeros on inactive steps)
        out_fused_k<<<D_ / 4, 256>>>(OU, fin, xout, fout);
    }
    // after 2 layers: attention input = spk0 (B,T,S,D)

    // -------- attention (single-pass tf32) --------
    transpose_k<<<(int)(SPK / 256), 256>>>(spk0, xp);
    const int MA = NROWS;  // 32768
    gemm_tf32_k<true><<<dim3(D_ / 128, MA / 128), 256>>>(xp, wq, bq, qb, MA, D_, D_);
    gemm_tf32_k<true><<<dim3(D_ / 128, MA / 128), 256>>>(xp, wk, bk, kb, MA, D_, D_);
    gemm_tf32_k<true><<<dim3(D_ / 128, MA / 128), 256>>>(xp, wv, bv, vb, MA, D_, D_);
    attn_core_k<<<NTOK * 4, 128>>>(qb, kb, vb, spk1);           // av -> spk1
    gemm_tf32_k<true><<<dim3(D_ / 128, MA / 128), 256>>>(spk1, wo, bo, kb, MA, D_, D_);

    // -------- residual + mean + outputs --------
    float* hout = ((long)out_size >= LOGITS_SZ + H_SZ) ? (out + LOGITS_SZ) : xp;
    finalize_k<<<(NTOK * D_) / 256, 256>>>(spk0, kb, hout, hmean);

    // logits (single-pass tf32)
    gemm_tf32_k<true><<<dim3(V_ / 128, NTOK / 128), 256>>>(
        hmean, wout, bout, out, NTOK, V_, D_);
}

// round 13
// speedup vs baseline: 2.7345x; 1.1724x over previous
#include <cuda_runtime.h>
#include <cuda_bf16.h>
#include <math.h>

// ---------------------------------------------------------------------------
// Problem constants
// ---------------------------------------------------------------------------
#define B_    4
#define S_    512
#define T_    16
#define D_    512
#define DS_   64
#define V_    32000
#define NTOK  2048              // B_*S_
#define NROWS 32768             // B_*T_*S_
#define DECAY 0.60653065971263342f   // exp(-1/2)
#define NBLK  128               // persistent state kernel grid

static const long SPK       = (long)NROWS * D_;   // 16,777,216 floats
static const long LOGITS_SZ = (long)NTOK * V_;    // 65,536,000 floats
static const long H_SZ      = SPK;

// arena offsets (floats)
static const long OFF_SPK0 = 0;
static const long OFF_SPK1 = SPK;
static const long OFF_XP   = 2 * SPK;
static const long OFF_Q    = 3 * SPK;             // doubles as OU (32768x512)
static const long OFF_K    = 4 * SPK;
static const long OFF_V    = 5 * SPK;
static const long OFF_HM   = 6 * SPK;                       // 2048 x 512
static const long OFF_CNT  = OFF_HM + (long)NTOK * D_;      // ints: 16*64
static const long CNT_INTS = 16 * 64;
static const long OFF_BAR  = OFF_CNT + CNT_INTS;            // 16 ints
static const long OFF_FLG  = OFF_BAR + 16;                  // 48 ints
static const long OFF_HALL = OFF_FLG + 64;                  // 32768 x 64
static const long ARENA_TOTAL = OFF_HALL + (long)NROWS * DS_;

__device__ __align__(256) float g_arena[ARENA_TOTAL];

// persistent state kernel smem layout (floats)
#define SM_AT    0                    // At[n][m] : 64 x 65
#define SM_BT    (64 * 65)            // Bt[d][m] : 512 x 65
#define SM_XS    (SM_BT + 512 * 65)   // xs[tk][d]: 16 x 512
#define SM_HS    (SM_XS + 16 * 512)   // hs[tk][m]: 16 x 68
#define SM_INT   (SM_HS + 16 * 68)    // scnt[64] + sflag[16]
#define SM_TOTAL (SM_INT + 80)
static const int SMEM_STATE_BYTES = SM_TOTAL * 4;   // 187,520 B

// ===========================================================================
// SSM SECTION -- LIF arithmetic BITWISE-IDENTICAL to R12 (passing).
// ===========================================================================

__global__ void encode_k(const int* __restrict__ ids, const float* __restrict__ emb,
                         const float* __restrict__ scaling,
                         float* __restrict__ spk, int* __restrict__ flag)
{
    int idx = blockIdx.x * blockDim.x + threadIdx.x;   // over NTOK*D_
    int d   = idx & (D_ - 1);
    int tok = idx >> 9;
    int b   = tok >> 9;
    int s   = tok & (S_ - 1);
    float e = emb[(long)ids[tok] * D_ + d];
    float a = 1.0f / (1.0f + expf(-(*scaling) * e));
    float tr = rintf(10.0f * (1.0f - a));
    int ti = (int)tr;
    if (ti < 0) ti = 0;
    if (ti > T_ - 1) ti = T_ - 1;
    spk[(((long)(b * T_ + ti)) * S_ + s) * D_ + d] = 1.0f;
    flag[ti] = 1;
}

// Persistent per-layer state recurrence: 128 blocks x 256 threads, 1/SM.
__global__ __launch_bounds__(256)
void state_layer_k(const float* __restrict__ spk_in,
                   const float* __restrict__ Amat, const float* __restrict__ Bmat,
                   int* __restrict__ cnt, const int* __restrict__ flags,
                   float* __restrict__ Hall, int* __restrict__ bar)
{
    extern __shared__ float sm[];
    float* At = sm + SM_AT;
    float* Bt = sm + SM_BT;
    float* xs = sm + SM_XS;
    float* hs = sm + SM_HS;
    int*   scnt  = (int*)(sm + SM_INT);
    int*   sflag = scnt + 64;

    const int tid  = threadIdx.x;
    const int m    = tid & 63;
    const int lt   = tid >> 6;          // 0..3
    const int tok0 = blockIdx.x * 16;

    for (int i = tid; i < DS_ * DS_; i += 256) {
        int r = i >> 6, n = i & 63;
        At[n * 65 + r] = Amat[i];
    }
    for (int i = tid; i < DS_ * D_; i += 256) {
        int mm = i >> 9, d = i & (D_ - 1);
        Bt[d * 65 + mm] = Bmat[i];
    }
    for (int i = tid; i < 16 * 68; i += 256) hs[i] = 0.0f;
    if (tid < 16) sflag[tid] = flags[tid];
    __syncthreads();

    float v[4];
#pragma unroll
    for (int j = 0; j < 4; ++j) v[j] = 0.0f;
    float thr = 1.0f;

    for (int t = 0; t < T_; ++t) {
        const int active = sflag[t];
        if (tid < 64) scnt[tid] = 0;
        if (active) {
            for (int i = tid; i < 16 * D_; i += 256) {
                int tk = i >> 9, d = i & (D_ - 1);
                int tok = tok0 + tk;
                int b = tok >> 9, s = tok & (S_ - 1);
                xs[tk * D_ + d] = spk_in[(((long)(b * T_ + t)) * S_ + s) * D_ + d];
            }
        }
        __syncthreads();

        float acc[4];
#pragma unroll
        for (int j = 0; j < 4; ++j) acc[j] = 0.0f;

        for (int n = 0; n < DS_; n += 4) {
            float a0 = At[(n + 0) * 65 + m];
            float a1 = At[(n + 1) * 65 + m];
            float a2 = At[(n + 2) * 65 + m];
            float a3 = At[(n + 3) * 65 + m];
#pragma unroll
            for (int j = 0; j < 4; ++j) {
                float4 hv = *(const float4*)&hs[(lt + 4 * j) * 68 + n];
                acc[j] += hv.x * a0;
                acc[j] += hv.y * a1;
                acc[j] += hv.z * a2;
                acc[j] += hv.w * a3;
            }
        }
        if (active) {
            for (int d = 0; d < D_; d += 4) {
                float b0 = Bt[(d + 0) * 65 + m];
                float b1 = Bt[(d + 1) * 65 + m];
                float b2 = Bt[(d + 2) * 65 + m];
                float b3 = Bt[(d + 3) * 65 + m];
#pragma unroll
                for (int j = 0; j < 4; ++j) {
                    float4 xv = *(const float4*)&xs[(lt + 4 * j) * D_ + d];
                    acc[j] += xv.x * b0;
                    acc[j] += xv.y * b1;
                    acc[j] += xv.z * b2;
                    acc[j] += xv.w * b3;
                }
            }
        }
        __syncthreads();

        int c = 0;
#pragma unroll
        for (int j = 0; j < 4; ++j) {
            int tk = lt + 4 * j;
            int tok = tok0 + tk;
            float vv = v[j] * DECAY + acc[j];
            float sp = (vv - thr >= 0.0f) ? 1.0f : 0.0f;
            v[j] = vv * (1.0f - sp);
            hs[tk * 68 + m] = sp;
            int b = tok >> 9, s = tok & (S_ - 1);
            Hall[(((long)(b * T_ + t)) * S_ + s) * DS_ + m] = sp;
            c += (int)sp;
        }
        if (c) atomicAdd(&scnt[m], c);
        __syncthreads();
        if (tid < 64 && scnt[tid]) atomicAdd(&cnt[t * 64 + tid], scnt[tid]);
        __threadfence();
        if (tid == 0) {
            atomicAdd(bar, 1);
            while (*((volatile int*)bar) < NBLK * (t + 1)) { }
        }
        __syncthreads();
        {
            float mean = (float)(*((volatile int*)&cnt[t * 64 + m])) * (1.0f / 2048.0f);
            thr += 0.1f * (mean - 0.1f);
        }
        __syncthreads();
    }
}

// Fused output LIF over all 16 steps (unchanged -- passing).
__global__ __launch_bounds__(256)
void out_fused_k(const float* __restrict__ OU, const int* __restrict__ flags,
                 float* __restrict__ spk_out, int* __restrict__ flags_next)
{
    const int tid = threadIdx.x;
    const int el  = tid & 3;
    const int e   = blockIdx.x * 4 + el;
    const int ts  = tid >> 2;                 // 0..63
    __shared__ int scnt[4];

    float v[32];
#pragma unroll
    for (int j = 0; j < 32; ++j) v[j] = 0.0f;
    float thr = 1.0f;

    for (int t = 0; t < T_; ++t) {
        int act = flags[t];
        if (tid < 4) scnt[tid] = 0;
        __syncthreads();
        if (act) {
            int c = 0;
#pragma unroll
            for (int j = 0; j < 32; ++j) {
                int tok = ts + 64 * j;
                int b = tok >> 9, s = tok & (S_ - 1);
                long row = (long)b * (T_ * S_) + (long)t * S_ + s;
                float vv = v[j] * DECAY + OU[row * D_ + e];
                float sp = (vv - thr >= 0.0f) ? 1.0f : 0.0f;
                v[j] = vv * (1.0f - sp);
                spk_out[row * D_ + e] = sp;
                c += (int)sp;
            }
            if (c) atomicAdd(&scnt[el], c);
        } else {
#pragma unroll
            for (int j = 0; j < 32; ++j) {
                int tok = ts + 64 * j;
                int b = tok >> 9, s = tok & (S_ - 1);
                long row = (long)b * (T_ * S_) + (long)t * S_ + s;
                spk_out[row * D_ + e] = 0.0f;
            }
        }
        __syncthreads();
        if (act) {
            int cc = scnt[el];
            float mean = (float)cc * (1.0f / 2048.0f);
            thr += 0.1f * (mean - 0.1f);
            if (tid == 0 && (scnt[0] | scnt[1] | scnt[2] | scnt[3]))
                flags_next[t] = 1;
        }
        __syncthreads();
    }
}

// fp32 SGEMM -- double-buffered; per-output FFMA chain (ascending k) is
// BITWISE-IDENTICAL to the R12 version. Optional per-t gating: row-block by
// maps to t = (by>>2)&15; OU rows of inactive steps are never read downstream.
template<bool ACC, bool HASBIAS>
__global__ __launch_bounds__(256)
void sgemm_k(const float* __restrict__ A, const float* __restrict__ W,
             const float* __restrict__ bias, float* __restrict__ C,
             int M, int N, int K,
             long aOuter, long aInner, long aConst, int aSdiv,
             const int* __restrict__ tflags)
{
    const int bx = blockIdx.x, by = blockIdx.y;
    if (tflags && tflags[(by >> 2) & (T_ - 1)] == 0) return;

    __shared__ float As[2][8][128];
    __shared__ float Bs[2][8][128];
    const int tid = threadIdx.x;
    const int tx = tid & 15, ty = tid >> 4;

    const int lrow = tid >> 1;
    const int lk4  = (tid & 1) * 4;

    const int arow = by * 128 + lrow;
    const long aoff = (long)(arow / aSdiv) * aOuter + (long)(arow % aSdiv) * aInner + aConst;
    const float* Aptr = A + aoff + lk4;
    const float* Wptr = W + (long)(bx * 128 + lrow) * K + lk4;

    float acc[8][8];
#pragma unroll
    for (int i = 0; i < 8; ++i)
#pragma unroll
        for (int j = 0; j < 8; ++j) acc[i][j] = 0.0f;

    // prologue: tile 0 -> buf 0
    {
        float4 av = *(const float4*)(Aptr);
        float4 wv = *(const float4*)(Wptr);
        As[0][lk4 + 0][lrow] = av.x; As[0][lk4 + 1][lrow] = av.y;
        As[0][lk4 + 2][lrow] = av.z; As[0][lk4 + 3][lrow] = av.w;
        Bs[0][lk4 + 0][lrow] = wv.x; Bs[0][lk4 + 1][lrow] = wv.y;
        Bs[0][lk4 + 2][lrow] = wv.z; Bs[0][lk4 + 3][lrow] = wv.w;
    }
    __syncthreads();

    const int ntiles = K / 8;
    for (int tile = 0; tile < ntiles; ++tile) {
        const int cur = tile & 1;
        float4 av, wv;
        const bool more = (tile + 1 < ntiles);
        if (more) {
            av = *(const float4*)(Aptr + (tile + 1) * 8);
            wv = *(const float4*)(Wptr + (tile + 1) * 8);
        }
#pragma unroll
        for (int k = 0; k < 8; ++k) {
            float ar[8], br[8];
            *(float4*)&ar[0] = *(const float4*)&As[cur][k][ty * 4];
            *(float4*)&ar[4] = *(const float4*)&As[cur][k][64 + ty * 4];
            *(float4*)&br[0] = *(const float4*)&Bs[cur][k][tx * 4];
            *(float4*)&br[4] = *(const float4*)&Bs[cur][k][64 + tx * 4];
#pragma unroll
            for (int i = 0; i < 8; ++i)
#pragma unroll
                for (int j = 0; j < 8; ++j)
                    acc[i][j] += ar[i] * br[j];
        }
        if (more) {
            const int nxt = cur ^ 1;
            As[nxt][lk4 + 0][lrow] = av.x; As[nxt][lk4 + 1][lrow] = av.y;
            As[nxt][lk4 + 2][lrow] = av.z; As[nxt][lk4 + 3][lrow] = av.w;
            Bs[nxt][lk4 + 0][lrow] = wv.x; Bs[nxt][lk4 + 1][lrow] = wv.y;
            Bs[nxt][lk4 + 2][lrow] = wv.z; Bs[nxt][lk4 + 3][lrow] = wv.w;
        }
        __syncthreads();
    }

#pragma unroll
    for (int i = 0; i < 8; ++i) {
        int row = by * 128 + ((i < 4) ? (ty * 4 + i) : (64 + ty * 4 + (i - 4)));
        float* crow = C + (long)row * N + bx * 128;
#pragma unroll
        for (int half = 0; half < 2; ++half) {
            int colbase = half * 64 + tx * 4;
            float4 r;
            r.x = acc[i][half * 4 + 0]; r.y = acc[i][half * 4 + 1];
            r.z = acc[i][half * 4 + 2]; r.w = acc[i][half * 4 + 3];
            if (HASBIAS) {
                float4 bv = *(const float4*)(bias + bx * 128 + colbase);
                r.x += bv.x; r.y += bv.y; r.z += bv.z; r.w += bv.w;
            }
            if (ACC) {
                float4 ov = *(const float4*)(crow + colbase);
                r.x += ov.x; r.y += ov.y; r.z += ov.z; r.w += ov.w;
            }
            *(float4*)(crow + colbase) = r;
        }
    }
}

// ===========================================================================
// TENSOR-CORE SECTION -- single-pass tf32, double-buffered (mma sequence per
// output unchanged => results bitwise identical to R12's tf32 GEMM).
// ===========================================================================
__device__ __forceinline__ unsigned f2tf(float x) {
    unsigned u;
    asm("cvt.rna.tf32.f32 %0, %1;" : "=r"(u) : "f"(x));
    return u;
}

__device__ __forceinline__ void mma8(float* c, const unsigned* a, const unsigned* b) {
    asm volatile(
        "mma.sync.aligned.m16n8k8.row.col.f32.tf32.tf32.f32 "
        "{%0,%1,%2,%3},{%4,%5,%6,%7},{%8,%9},{%0,%1,%2,%3};"
        : "+f"(c[0]), "+f"(c[1]), "+f"(c[2]), "+f"(c[3])
        : "r"(a[0]), "r"(a[1]), "r"(a[2]), "r"(a[3]), "r"(b[0]), "r"(b[1]));
}

template<bool HASBIAS>
__global__ __launch_bounds__(256)
void gemm_tf32_k(const float* __restrict__ A, const float* __restrict__ W,
                 const float* __restrict__ bias, float* __restrict__ C,
                 int M, int N, int K)
{
    constexpr int BM = 128, BN = 128, BK = 16;
    constexpr int MT = 4, NT = 4;
    __shared__ float As[2][BK][BM + 8];
    __shared__ float Bs[2][BK][BN + 8];

    const int tid  = threadIdx.x;
    const int warp = tid >> 5, lane = tid & 31;
    const int wm = warp & 1, wn = warp >> 1;
    const int mW = wm * 64, nW = wn * 32;
    const int g = lane >> 2, q = lane & 3;
    const int bx = blockIdx.x, by = blockIdx.y;

    const int lr = tid >> 1;
    const int lk = (tid & 1) * 8;
    const float* Ag = A + (long)(by * BM + lr) * K + lk;
    const float* Wg = W + (long)(bx * BN + lr) * K + lk;

    float acc[MT][NT][4];
#pragma unroll
    for (int i = 0; i < MT; ++i)
#pragma unroll
        for (int j = 0; j < NT; ++j)
#pragma unroll
            for (int r = 0; r < 4; ++r) acc[i][j][r] = 0.0f;

    // prologue: tile 0 -> buf 0
    {
        float4 a0 = *(const float4*)(Ag);
        float4 a1 = *(const float4*)(Ag + 4);
        As[0][lk + 0][lr] = a0.x; As[0][lk + 1][lr] = a0.y;
        As[0][lk + 2][lr] = a0.z; As[0][lk + 3][lr] = a0.w;
        As[0][lk + 4][lr] = a1.x; As[0][lk + 5][lr] = a1.y;
        As[0][lk + 6][lr] = a1.z; As[0][lk + 7][lr] = a1.w;
        float4 w0 = *(const float4*)(Wg);
        float4 w1 = *(const float4*)(Wg + 4);
        Bs[0][lk + 0][lr] = w0.x; Bs[0][lk + 1][lr] = w0.y;
        Bs[0][lk + 2][lr] = w0.z; Bs[0][lk + 3][lr] = w0.w;
        Bs[0][lk + 4][lr] = w1.x; Bs[0][lk + 5][lr] = w1.y;
        Bs[0][lk + 6][lr] = w1.z; Bs[0][lk + 7][lr] = w1.w;
    }
    __syncthreads();

    const int ntiles = K / BK;
    for (int tile = 0; tile < ntiles; ++tile) {
        const int cur = tile & 1;
        const bool more = (tile + 1 < ntiles);
        float4 a0, a1, w0, w1;
        if (more) {
            a0 = *(const float4*)(Ag + (tile + 1) * BK);
            a1 = *(const float4*)(Ag + (tile + 1) * BK + 4);
            w0 = *(const float4*)(Wg + (tile + 1) * BK);
            w1 = *(const float4*)(Wg + (tile + 1) * BK + 4);
        }
#pragma unroll
        for (int ks = 0; ks < BK; ks += 8) {
            unsigned af[MT][4];
            unsigned bf[NT][2];
#pragma unroll
            for (int i = 0; i < MT; ++i) {
                int m = mW + i * 16 + g;
                af[i][0] = f2tf(As[cur][ks + q][m]);
                af[i][1] = f2tf(As[cur][ks + q][m + 8]);
                af[i][2] = f2tf(As[cur][ks + 4 + q][m]);
                af[i][3] = f2tf(As[cur][ks + 4 + q][m + 8]);
            }
#pragma unroll
            for (int j = 0; j < NT; ++j) {
                int n = nW + j * 8 + g;
                bf[j][0] = f2tf(Bs[cur][ks + q][n]);
                bf[j][1] = f2tf(Bs[cur][ks + 4 + q][n]);
            }
#pragma unroll
            for (int i = 0; i < MT; ++i)
#pragma unroll
                for (int j = 0; j < NT; ++j)
                    mma8(acc[i][j], af[i], bf[j]);
        }
        if (more) {
            const int nxt = cur ^ 1;
            As[nxt][lk + 0][lr] = a0.x; As[nxt][lk + 1][lr] = a0.y;
            As[nxt][lk + 2][lr] = a0.z; As[nxt][lk + 3][lr] = a0.w;
            As[nxt][lk + 4][lr] = a1.x; As[nxt][lk + 5][lr] = a1.y;
            As[nxt][lk + 6][lr] = a1.z; As[nxt][lk + 7][lr] = a1.w;
            Bs[nxt][lk + 0][lr] = w0.x; Bs[nxt][lk + 1][lr] = w0.y;
            Bs[nxt][lk + 2][lr] = w0.z; Bs[nxt][lk + 3][lr] = w0.w;
            Bs[nxt][lk + 4][lr] = w1.x; Bs[nxt][lk + 5][lr] = w1.y;
            Bs[nxt][lk + 6][lr] = w1.z; Bs[nxt][lk + 7][lr] = w1.w;
        }
        __syncthreads();
    }

#pragma unroll
    for (int i = 0; i < MT; ++i) {
        int r0 = by * BM + mW + i * 16 + g;
#pragma unroll
        for (int j = 0; j < NT; ++j) {
            int c0 = bx * BN + nW + j * 8 + q * 2;
            float2 lo; lo.x = acc[i][j][0]; lo.y = acc[i][j][1];
            float2 hi; hi.x = acc[i][j][2]; hi.y = acc[i][j][3];
            if (HASBIAS) {
                float2 bv = *(const float2*)(bias + c0);
                lo.x += bv.x; lo.y += bv.y; hi.x += bv.x; hi.y += bv.y;
            }
            *(float2*)(C + (long)r0 * N + c0)       = lo;
            *(float2*)(C + (long)(r0 + 8) * N + c0) = hi;
        }
    }
}

// ---------------------------------------------------------------------------
// (B,T,S,D) -> (B,S,T,D) permute
// ---------------------------------------------------------------------------
__global__ void transpose_k(const float* __restrict__ x, float* __restrict__ xp)
{
    long idx = (long)blockIdx.x * blockDim.x + threadIdx.x;
    int d = idx & (D_ - 1);
    long r = idx >> 9;
    int t = (int)(r & (T_ - 1));
    long r2 = r >> 4;
    int s = (int)(r2 & (S_ - 1));
    int b = (int)(r2 >> 9);
    xp[idx] = x[(((long)(b * T_ + t)) * S_ + s) * D_ + d];
}

// ---------------------------------------------------------------------------
// Attention core per (token, head)
// ---------------------------------------------------------------------------
__global__ __launch_bounds__(128)
void attn_core_k(const float* __restrict__ q, const float* __restrict__ k,
                 const float* __restrict__ v, float* __restrict__ av)
{
    __shared__ float qs[16][128], ks[16][128], vsm[16][128];
    __shared__ float sc[16][17];
    const int tid = threadIdx.x;
    const long token = blockIdx.x >> 2;
    const int h = blockIdx.x & 3;
    const long base = token * 16 * 512 + h * 128;

#pragma unroll
    for (int t = 0; t < 16; ++t) {
        qs[t][tid]  = q[base + (long)t * 512 + tid];
        ks[t][tid]  = k[base + (long)t * 512 + tid];
        vsm[t][tid] = v[base + (long)t * 512 + tid];
    }
    __syncthreads();

    for (int p = tid; p < 256; p += 128) {
        int t = p >> 4, u = p & 15;
        float acc = 0.0f;
#pragma unroll
        for (int d = 0; d < 128; ++d) acc += qs[t][d] * ks[u][d];
        sc[t][u] = acc / 11.3137084989847612f;   // / sqrt(128)
    }
    __syncthreads();

    if (tid < 16) {
        int t = tid;
        float mx = sc[t][0];
#pragma unroll
        for (int u = 1; u < 16; ++u) mx = fmaxf(mx, sc[t][u]);
        float e[16], sum = 0.0f;
#pragma unroll
        for (int u = 0; u < 16; ++u) { e[u] = expf(sc[t][u] - mx); sum += e[u]; }
#pragma unroll
        for (int u = 0; u < 16; ++u) sc[t][u] = e[u] / sum;
    }
    __syncthreads();

#pragma unroll
    for (int t = 0; t < 16; ++t) {
        float acc = 0.0f;
#pragma unroll
        for (int u = 0; u < 16; ++u) acc += sc[t][u] * vsm[u][tid];
        av[base + (long)t * 512 + tid] = acc;
    }
}

// ---------------------------------------------------------------------------
// h = x + permute(out_attn); hmean = mean_t(h)
// ---------------------------------------------------------------------------
__global__ void finalize_k(const float* __restrict__ xspk, const float* __restrict__ oat,
                           float* __restrict__ hout, float* __restrict__ hmean)
{
    int idx = blockIdx.x * blockDim.x + threadIdx.x;  // over NTOK*D_
    int d   = idx & (D_ - 1);
    int tok = idx >> 9;
    int b   = tok >> 9;
    int s   = tok & (S_ - 1);
    float sum = 0.0f;
#pragma unroll
    for (int t = 0; t < 16; ++t) {
        long hidx = (((long)(b * T_ + t)) * S_ + s) * D_ + d;
        float val = xspk[hidx] + oat[(((long)tok) * T_ + t) * D_ + d];
        hout[hidx] = val;
        sum += val;
    }
    hmean[(long)tok * D_ + d] = sum * (1.0f / 16.0f);
}

// ---------------------------------------------------------------------------
// host
// ---------------------------------------------------------------------------
extern "C" void kernel_launch(void* const* d_in, const int* in_sizes, int n_in,
                              void* d_out, int out_size)
{
    const int*   ids  = (const int*)d_in[0];
    const float* emb  = (const float*)d_in[1];
    const float* scal = (const float*)d_in[2];
    const float* Aall = (const float*)d_in[3];
    const float* Ball = (const float*)d_in[4];
    const float* Call = (const float*)d_in[5];
    const float* Dall = (const float*)d_in[6];
    const float* wq = (const float*)d_in[7];   const float* bq = (const float*)d_in[8];
    const float* wk = (const float*)d_in[9];   const float* bk = (const float*)d_in[10];
    const float* wv = (const float*)d_in[11];  const float* bv = (const float*)d_in[12];
    const float* wo = (const float*)d_in[13];  const float* bo = (const float*)d_in[14];
    const float* wout = (const float*)d_in[15];const float* bout = (const float*)d_in[16];
    float* out = (float*)d_out;

    float* arena = nullptr;
    cudaGetSymbolAddress((void**)&arena, g_arena);

    float* spk0   = arena + OFF_SPK0;
    float* spk1   = arena + OFF_SPK1;
    float* xp     = arena + OFF_XP;
    float* qb     = arena + OFF_Q;     // OU during SSM phase
    float* kb     = arena + OFF_K;
    float* vb     = arena + OFF_V;
    float* hmean  = arena + OFF_HM;
    int*   cnt    = (int*)(arena + OFF_CNT);   // 16*64 state counts
    int*   bar    = (int*)(arena + OFF_BAR);
    int*   flags  = (int*)(arena + OFF_FLG);
    float* Hall   = arena + OFF_HALL;
    float* OU     = qb;

    cudaFuncSetAttribute(state_layer_k,
                         cudaFuncAttributeMaxDynamicSharedMemorySize,
                         SMEM_STATE_BYTES);

    // -------- encode --------
    cudaMemsetAsync(spk0, 0, SPK * sizeof(float));
    cudaMemsetAsync(flags, 0, 48 * sizeof(int));
    encode_k<<<(NTOK * D_) / 256, 256>>>(ids, emb, scal, spk0, flags);

    // -------- SSM layers --------
    for (int l = 0; l < 2; ++l) {
        const float* Al = Aall + (long)l * DS_ * DS_;
        const float* Bl = Ball + (long)l * DS_ * D_;
        const float* Cl = Call + (long)l * D_ * DS_;
        const float* Dl = Dall + (long)l * D_ * D_;
        float* xin  = l ? spk1 : spk0;
        float* xout = l ? spk0 : spk1;
        int* fin  = flags + (l ? 16 : 0);
        int* fout = flags + (l ? 32 : 16);

        cudaMemsetAsync(cnt, 0, (CNT_INTS + 16) * sizeof(int));

        // persistent state recurrence: all 16 steps in one launch
        state_layer_k<<<NBLK, 256, SMEM_STATE_BYTES>>>(
            xin, Al, Bl, cnt, fin, Hall, bar);

        // hoisted output-path GEMMs (chains bitwise == R12); rows of inactive
        // steps are skipped -- out_fused never reads them.
        sgemm_k<false, false><<<dim3(4, NROWS / 128), 256>>>(
            Hall, Cl, nullptr, OU, NROWS, D_, DS_,
            (long)NROWS * DS_, (long)DS_, 0L, NROWS, fin);
        sgemm_k<true, false><<<dim3(4, NROWS / 128), 256>>>(
            xin, Dl, nullptr, OU, NROWS, D_, D_,
            (long)NROWS * D_, (long)D_, 0L, NROWS, fin);

        // fused output LIF over all 16 steps (writes zeros on inactive steps)
        out_fused_k<<<D_ / 4, 256>>>(OU, fin, xout, fout);
    }
    // after 2 layers: attention input = spk0 (B,T,S,D)

    // -------- attention (single-pass tf32) --------
    transpose_k<<<(int)(SPK / 256), 256>>>(spk0, xp);
    const int MA = NROWS;  // 32768
    gemm_tf32_k<true><<<dim3(D_ / 128, MA / 128), 256>>>(xp, wq, bq, qb, MA, D_, D_);
    gemm_tf32_k<true><<<dim3(D_ / 128, MA / 128), 256>>>(xp, wk, bk, kb, MA, D_, D_);
    gemm_tf32_k<true><<<dim3(D_ / 128, MA / 128), 256>>>(xp, wv, bv, vb, MA, D_, D_);
    attn_core_k<<<NTOK * 4, 128>>>(qb, kb, vb, spk1);           // av -> spk1
    gemm_tf32_k<true><<<dim3(D_ / 128, MA / 128), 256>>>(spk1, wo, bo, kb, MA, D_, D_);

    // -------- residual + mean + outputs --------
    float* hout = ((long)out_size >= LOGITS_SZ + H_SZ) ? (out + LOGITS_SZ) : xp;
    finalize_k<<<(NTOK * D_) / 256, 256>>>(spk0, kb, hout, hmean);

    // logits (single-pass tf32)
    gemm_tf32_k<true><<<dim3(V_ / 128, NTOK / 128), 256>>>(
        hmean, wout, bout, out, NTOK, V_, D_);
}